// round 13
// baseline (speedup 1.0000x reference)
#include <cuda_runtime.h>
#include <cuda_fp16.h>
#include <float.h>
#include <math.h>
#include <stdint.h>

// Problem constants
#define B_   2
#define S_   2048
#define E_   4096
#define HQ_  32
#define HKV_ 8
#define D_   128
#define M_   (B_ * S_)          // 4096
#define SCALE_ 0.015625f        // 1/sqrt(4096)
#define LOG2E_ 1.44269504088896f

// ---------------------------------------------------------------------------
// Scratch
// ---------------------------------------------------------------------------
__device__ __half g_xH [(size_t)M_ * E_];             // x fp16 [M][K]
__device__ __half g_wqT[(size_t)(HQ_ * D_) * E_];     // wq^T [N][K]
__device__ __half g_wkT[(size_t)(HKV_ * D_) * E_];    // wk^T
__device__ __half g_wvT[(size_t)(HKV_ * D_) * E_];    // wv^T
__device__ __half g_woT[(size_t)E_ * (HQ_ * D_)];     // wo^T
__device__ __half g_Qb [(size_t)B_ * HQ_ * S_ * D_];  // roped+scaled(log2e) Q [b,h,s,d]
__device__ __half g_Kc [(size_t)B_ * HKV_ * S_ * D_]; // roped K cache   [b,h,pos,d]
__device__ __half g_Vc [(size_t)B_ * HKV_ * D_ * S_]; // V cache transposed [b,h,d,pos]
__device__ __half g_AO [(size_t)M_ * (HQ_ * D_)];     // attn out fp16

// ---------------------------------------------------------------------------
// helpers
// ---------------------------------------------------------------------------
__device__ __forceinline__ void mma_f16(float* c, const uint32_t* a, const uint32_t* b) {
    asm volatile(
        "mma.sync.aligned.m16n8k16.row.col.f32.f16.f16.f32 "
        "{%0,%1,%2,%3},{%4,%5,%6,%7},{%8,%9},{%0,%1,%2,%3};"
        : "+f"(c[0]), "+f"(c[1]), "+f"(c[2]), "+f"(c[3])
        : "r"(a[0]), "r"(a[1]), "r"(a[2]), "r"(a[3]), "r"(b[0]), "r"(b[1]));
}
__device__ __forceinline__ void ldsm_x4(uint32_t* r, uint32_t addr) {
    asm volatile("ldmatrix.sync.aligned.m8n8.x4.shared.b16 {%0,%1,%2,%3}, [%4];"
        : "=r"(r[0]), "=r"(r[1]), "=r"(r[2]), "=r"(r[3]) : "r"(addr));
}
__device__ __forceinline__ void cp16s(uint32_t saddr, const void* gmem) {
    asm volatile("cp.async.cg.shared.global [%0], [%1], 16;\n" :: "r"(saddr), "l"(gmem));
}
#define CP_COMMIT() asm volatile("cp.async.commit_group;\n" ::: "memory")
#define CP_WAIT(n)  asm volatile("cp.async.wait_group %0;\n" :: "n"(n) : "memory")
__device__ __forceinline__ uint32_t smem_u32(const void* p) {
    return (uint32_t)__cvta_generic_to_shared(p);
}
__device__ __forceinline__ uint32_t pack_h2(float a, float b) {
    __half2 h = __floats2half2_rn(a, b);
    return *(uint32_t*)&h;
}
__device__ __forceinline__ float ex2(float x) {
    float y;
    asm("ex2.approx.ftz.f32 %0, %1;" : "=f"(y) : "f"(x));
    return y;
}
// swizzled byte offsets (cp = 16B-chunk index within row)
#define OFF256(row, cp) ((uint32_t)((row) * 256 + (((((cp) & 7) ^ ((row) & 7)) | ((cp) & 8)) << 4)))
#define OFF128(row, cp) ((uint32_t)((row) * 128 + ((((cp) ^ ((row) & 7))) << 4)))

// ---------------------------------------------------------------------------
// Pre-pass: fp32 -> fp16 conversion of x; batched transpose of all 4 weights
// ---------------------------------------------------------------------------
__global__ void cvt_f16_arr(const float4* __restrict__ in, uint2* __restrict__ out, int n4) {
    int i = blockIdx.x * 256 + threadIdx.x;
    if (i < n4) {
        float4 v = in[i];
        out[i] = make_uint2(pack_h2(v.x, v.y), pack_h2(v.z, v.w));
    }
}
// All four weight transposes in ONE launch: [Kd][Nd] fp32 -> [Nd][Kd] fp16.
//   blocks [0,16384): wq   (Kd=4096, Nd=4096)
//   blocks [16384,20480): wk (Kd=4096, Nd=1024)
//   blocks [20480,24576): wv (Kd=4096, Nd=1024)
//   blocks [24576,40960): wo (Kd=4096, Nd=4096)
__global__ void cvt_transpose_all(
    const float* __restrict__ wq, const float* __restrict__ wk,
    const float* __restrict__ wv, const float* __restrict__ wo,
    __half* __restrict__ oq, __half* __restrict__ ok,
    __half* __restrict__ ov, __half* __restrict__ oo)
{
    __shared__ __half tb[32][33];
    const int bid = blockIdx.x;
    const float* in;
    __half* out;
    int Kd, Nd, bx, by;
    if (bid < 16384)      { in = wq; out = oq; Kd = E_; Nd = HQ_ * D_;
                            int r = bid;          bx = (r & 127) * 32; by = (r >> 7) * 32; }
    else if (bid < 20480) { in = wk; out = ok; Kd = E_; Nd = HKV_ * D_;
                            int r = bid - 16384;  bx = (r & 31) * 32;  by = (r >> 5) * 32; }
    else if (bid < 24576) { in = wv; out = ov; Kd = E_; Nd = HKV_ * D_;
                            int r = bid - 20480;  bx = (r & 31) * 32;  by = (r >> 5) * 32; }
    else                  { in = wo; out = oo; Kd = HQ_ * D_; Nd = E_;
                            int r = bid - 24576;  bx = (r & 127) * 32; by = (r >> 7) * 32; }
    const int x = threadIdx.x, y = threadIdx.y;   // block (32, 8)
    #pragma unroll
    for (int j = 0; j < 32; j += 8)
        tb[y + j][x] = __float2half(in[(size_t)(by + y + j) * Nd + bx + x]);
    __syncthreads();
    #pragma unroll
    for (int j = 0; j < 32; j += 8)
        out[(size_t)(bx + y + j) * Kd + by + x] = tb[x][y + j];
}

// ---------------------------------------------------------------------------
// fp16 GEMM: 128x128 CTA tile, 8 warps (2m x 4n), KC=64, 3-stage ring,
// ldmatrix fragments, 2 CTAs/SM.
//   MODE 0: fp32 C out (out-projection)
//   MODE 3: combined QKV projection: bx<32 Q | bx<40 K | else V
// ---------------------------------------------------------------------------
#define KCH 64
#define TILEB (128 * 128)
#define NSTG 3
#define GEMM_DSMEM (NSTG * 2 * TILEB)   // 96KB

template<int MODE>
__global__ __launch_bounds__(256, 2) void gemm_f16(
    const __half* __restrict__ A, const __half* __restrict__ Bq,
    const __half* __restrict__ Bk, const __half* __restrict__ Bv,
    float* __restrict__ C, __half* __restrict__ Oq, __half* __restrict__ Okk,
    __half* __restrict__ Ov,
    const float* __restrict__ fc, const int* __restrict__ ip,
    int M, int N, int K)
{
    extern __shared__ __align__(128) uint8_t dynraw[];
    const uint32_t smBase = smem_u32(dynraw);

    const int tid = threadIdx.x;
    const int lane = tid & 31, warp = tid >> 5;
    const int g = lane >> 2, t = lane & 3;
    const int wm = warp & 1, wn = warp >> 1;
    const int m0 = blockIdx.y * 128;

    const int l7 = lane & 7, l15 = lane & 15;
    const int lhi = lane >> 4, lb3 = (lane >> 3) & 1;

    const __half* Bt;
    int n0;
    int kind = 0;
    if (MODE == 3) {
        if (blockIdx.x < 32)      { Bt = Bq; n0 = blockIdx.x * 128;        kind = 0; }
        else if (blockIdx.x < 40) { Bt = Bk; n0 = (blockIdx.x - 32) * 128; kind = 1; }
        else                      { Bt = Bv; n0 = (blockIdx.x - 40) * 128; kind = 2; }
    } else {
        Bt = Bq; n0 = blockIdx.x * 128;
    }

    float acc[4][4][4] = {};

    auto load_chunk = [&](int ck, int st) {
        const uint32_t aB = smBase + st * TILEB;
        const uint32_t bB = smBase + NSTG * TILEB + st * TILEB;
        #pragma unroll
        for (int i = 0; i < 4; i++) {
            int c = i * 256 + tid;
            int row = c >> 3, cp = c & 7;
            uint32_t off = OFF128(row, cp);
            cp16s(aB + off, A  + (size_t)(m0 + row) * K + ck * KCH + cp * 8);
            cp16s(bB + off, Bt + (size_t)(n0 + row) * K + ck * KCH + cp * 8);
        }
        CP_COMMIT();
    };

    const int nchunk = K / KCH;
    load_chunk(0, 0);
    load_chunk(1, 1);

    for (int ci = 0; ci < nchunk; ci++) {
        const int s = ci % NSTG;
        if (ci + 1 < nchunk) { CP_WAIT(1); } else { CP_WAIT(0); }
        __syncthreads();
        if (ci + 2 < nchunk) load_chunk(ci + 2, (ci + 2) % NSTG);

        const uint32_t aB = smBase + s * TILEB;
        const uint32_t bB = smBase + NSTG * TILEB + s * TILEB;

        #pragma unroll
        for (int kk = 0; kk < 4; kk++) {
            uint32_t af[4][4], bf[2][4];
            #pragma unroll
            for (int mt = 0; mt < 4; mt++) {
                int row = wm * 64 + mt * 16 + l15;
                int ch  = 2 * kk + lhi;
                ldsm_x4(af[mt], aB + OFF128(row, ch));
            }
            #pragma unroll
            for (int p = 0; p < 2; p++) {
                int row = wn * 32 + p * 16 + lhi * 8 + l7;
                int ch  = 2 * kk + lb3;
                ldsm_x4(bf[p], bB + OFF128(row, ch));
            }
            #pragma unroll
            for (int mt = 0; mt < 4; mt++) {
                #pragma unroll
                for (int p = 0; p < 2; p++) {
                    mma_f16(acc[mt][2 * p],     af[mt], &bf[p][0]);
                    mma_f16(acc[mt][2 * p + 1], af[mt], &bf[p][2]);
                }
            }
        }
    }
    __syncthreads();

    if (MODE == 0) {
        #pragma unroll
        for (int mt = 0; mt < 4; mt++) {
            int r = m0 + wm * 64 + mt * 16 + g;
            #pragma unroll
            for (int nt = 0; nt < 4; nt++) {
                int cc = n0 + wn * 32 + nt * 8 + t * 2;
                *(float2*)(C + (size_t)r * N + cc)       = make_float2(acc[mt][nt][0], acc[mt][nt][1]);
                *(float2*)(C + (size_t)(r + 8) * N + cc) = make_float2(acc[mt][nt][2], acc[mt][nt][3]);
            }
        }
    } else {
        const bool doRope = (kind != 2);
        #pragma unroll
        for (int mt = 0; mt < 4; mt++) {
            int r = m0 + wm * 64 + mt * 16 + g;
            int b = r >> 11;
            int sA = r & (S_ - 1);
            int sB = sA + 8;
            #pragma unroll
            for (int nt = 0; nt < 4; nt++) {
                int cc = n0 + wn * 32 + nt * 8 + t * 2;
                int h  = cc >> 7;
                int dd = cc & (D_ - 1);
                int p  = dd >> 1;

                float a0 = acc[mt][nt][0], a1 = acc[mt][nt][1];
                float a2 = acc[mt][nt][2], a3 = acc[mt][nt][3];
                float o0, o1, o2, o3;
                if (doRope) {
                    float2 csA = ((const float2*)fc)[(size_t)sA * 64 + p];
                    float2 csB = ((const float2*)fc)[(size_t)sB * 64 + p];
                    o0 = a0 * csA.x - a1 * csA.y;
                    o1 = a0 * csA.y + a1 * csA.x;
                    o2 = a2 * csB.x - a3 * csB.y;
                    o3 = a2 * csB.y + a3 * csB.x;
                } else {
                    o0 = a0; o1 = a1; o2 = a2; o3 = a3;
                }

                if (kind == 0) {
                    // scale includes log2e for exp2-domain softmax
                    const float sc2 = SCALE_ * LOG2E_;
                    o0 *= sc2; o1 *= sc2; o2 *= sc2; o3 *= sc2;
                    *(__half2*)(Oq + ((size_t)(b * HQ_ + h) * S_ + sA) * D_ + dd) = __floats2half2_rn(o0, o1);
                    *(__half2*)(Oq + ((size_t)(b * HQ_ + h) * S_ + sB) * D_ + dd) = __floats2half2_rn(o2, o3);
                } else if (kind == 1) {
                    int posA = ip[sA], posB = ip[sB];
                    *(__half2*)(Okk + ((size_t)(b * HKV_ + h) * S_ + posA) * D_ + dd) = __floats2half2_rn(o0, o1);
                    *(__half2*)(Okk + ((size_t)(b * HKV_ + h) * S_ + posB) * D_ + dd) = __floats2half2_rn(o2, o3);
                } else {
                    int posA = ip[sA], posB = ip[sB];
                    size_t base = (size_t)(b * HKV_ + h) * D_;
                    Ov[(base + dd)     * S_ + posA] = __float2half(o0);
                    Ov[(base + dd + 1) * S_ + posA] = __float2half(o1);
                    Ov[(base + dd)     * S_ + posB] = __float2half(o2);
                    Ov[(base + dd + 1) * S_ + posB] = __float2half(o3);
                }
            }
        }
    }
}

// ---------------------------------------------------------------------------
// Fused flash attention (fp16, ldmatrix, exp2 softmax, diag-tile work skip)
// ---------------------------------------------------------------------------
#define SMQ_OFF  0
#define SMK_OFF  32768
#define SMV_OFF  (32768 + 2 * 16384)
#define FLASH_SMEM (32768 + 4 * 16384)

__device__ __forceinline__ void fa_load_kv_h(
    uint32_t smBase, int stage,
    const __half* __restrict__ Kp, const __half* __restrict__ Vtp,
    int kcol0, int tid)
{
    const uint32_t kB = smBase + SMK_OFF + stage * 16384;
    const uint32_t vB = smBase + SMV_OFF + stage * 16384;
    #pragma unroll
    for (int i = 0; i < 4; i++) {
        int c = i * 256 + tid;
        {
            int row = c >> 4, cp = c & 15;
            cp16s(kB + OFF256(row, cp), Kp + (size_t)row * D_ + cp * 8);
        }
        {
            int row = c >> 3, cp = c & 7;
            cp16s(vB + OFF128(row, cp), Vtp + (size_t)row * S_ + kcol0 + cp * 8);
        }
    }
    CP_COMMIT();
}

__global__ __launch_bounds__(256, 1) void flash_f16(
    const __half* __restrict__ Qb, const __half* __restrict__ Kc,
    const __half* __restrict__ Vc, __half* __restrict__ AO)
{
    extern __shared__ __align__(128) uint8_t smraw[];
    const uint32_t smBase = smem_u32(smraw);

    const int qt = (S_ / 128 - 1) - blockIdx.x;
    const int bh = blockIdx.y;
    const int b = bh / HQ_, h = bh % HQ_;
    const int kvh = h / (HQ_ / HKV_);
    const int m0 = qt * 128;

    const int tid = threadIdx.x, lane = tid & 31, warp = tid >> 5;
    const int g = lane >> 2, t = lane & 3;
    const int l7 = lane & 7, lhi = lane >> 4, lb3 = (lane >> 3) & 1;

    const __half* Qbase = Qb + (size_t)(b * HQ_ + h) * S_ * D_ + (size_t)m0 * D_;
    const __half* Kbase = Kc + (size_t)(b * HKV_ + kvh) * S_ * D_;
    const __half* Vtb   = Vc + (size_t)(b * HKV_ + kvh) * D_ * S_;

    #pragma unroll
    for (int i = 0; i < 8; i++) {
        int c = i * 256 + tid;
        int row = c >> 4, cp = c & 15;
        cp16s(smBase + SMQ_OFF + OFF256(row, cp), Qbase + (size_t)row * D_ + cp * 8);
    }
    CP_COMMIT();

    const int nkt = 2 * qt + 2;
    fa_load_kv_h(smBase, 0, Kbase, Vtb, 0, tid);

    uint32_t qf[8][4];
    float Oacc[16][4] = {};
    float mrow0 = -FLT_MAX, mrow1 = -FLT_MAX;
    float lrow0 = 0.f, lrow1 = 0.f;

    for (int kt = 0; kt < nkt; kt++) {
        const int s = kt & 1;
        if (kt + 1 < nkt) {
            fa_load_kv_h(smBase, s ^ 1, Kbase + (size_t)(kt + 1) * 64 * D_,
                         Vtb, (kt + 1) * 64, tid);
            CP_WAIT(1);
        } else {
            CP_WAIT(0);
        }
        __syncthreads();

        if (kt == 0) {
            const int qrow = warp * 16 + (lane & 15);
            #pragma unroll
            for (int ks = 0; ks < 8; ks++) {
                int ch = 2 * ks + lhi;
                ldsm_x4(qf[ks], smBase + SMQ_OFF + OFF256(qrow, ch));
            }
        }

        const uint32_t kB = smBase + SMK_OFF + s * 16384;
        const uint32_t vB = smBase + SMV_OFF + s * 16384;

        // per-warp fragment bounds (diag tiles have fully-masked fragments)
        const bool diag = (kt >= 2 * qt);
        int nf_max = 8, kk_max = 4;
        if (diag) {
            int lim = 16 * warp + 15 - (kt - 2 * qt) * 64;
            nf_max = (lim < 0) ? 0 : min(8, lim / 8 + 1);
            kk_max = (lim < 0) ? 0 : min(4, lim / 16 + 1);
        }

        // ---- S = Q K^T (exp2-domain scores; Q pre-scaled by SCALE*log2e) ----
        float sc[8][4];
        #pragma unroll
        for (int nf = 0; nf < 8; nf++)
            sc[nf][0] = sc[nf][1] = sc[nf][2] = sc[nf][3] = 0.f;   // 0 = masked P value
        #pragma unroll
        for (int ks = 0; ks < 8; ks++) {
            #pragma unroll
            for (int nfp = 0; nfp < 4; nfp++) {
                if (2 * nfp < nf_max) {
                    int krow = nfp * 16 + lhi * 8 + l7;
                    int ch   = 2 * ks + lb3;
                    uint32_t bb[4];
                    ldsm_x4(bb, kB + OFF256(krow, ch));
                    mma_f16(sc[2 * nfp], qf[ks], &bb[0]);
                    if (2 * nfp + 1 < nf_max)
                        mma_f16(sc[2 * nfp + 1], qf[ks], &bb[2]);
                }
            }
        }

        // ---- causal mask within computed fragments ----
        const int r0 = m0 + warp * 16 + g;
        const int r1 = r0 + 8;
        if (diag) {
            #pragma unroll
            for (int nf = 0; nf < 8; nf++) {
                if (nf < nf_max) {
                    int c0 = kt * 64 + nf * 8 + 2 * t;
                    if (c0     > r0) sc[nf][0] = -FLT_MAX;
                    if (c0 + 1 > r0) sc[nf][1] = -FLT_MAX;
                    if (c0     > r1) sc[nf][2] = -FLT_MAX;
                    if (c0 + 1 > r1) sc[nf][3] = -FLT_MAX;
                }
            }
        }

        // ---- online softmax (base-2) ----
        float mx0 = -FLT_MAX, mx1 = -FLT_MAX;
        #pragma unroll
        for (int nf = 0; nf < 8; nf++) {
            if (nf < nf_max) {
                mx0 = fmaxf(mx0, fmaxf(sc[nf][0], sc[nf][1]));
                mx1 = fmaxf(mx1, fmaxf(sc[nf][2], sc[nf][3]));
            }
        }
        mx0 = fmaxf(mx0, __shfl_xor_sync(0xffffffffu, mx0, 1));
        mx0 = fmaxf(mx0, __shfl_xor_sync(0xffffffffu, mx0, 2));
        mx1 = fmaxf(mx1, __shfl_xor_sync(0xffffffffu, mx1, 1));
        mx1 = fmaxf(mx1, __shfl_xor_sync(0xffffffffu, mx1, 2));

        float mnew0 = fmaxf(mrow0, mx0), mnew1 = fmaxf(mrow1, mx1);
        float f0 = ex2(mrow0 - mnew0), f1 = ex2(mrow1 - mnew1);
        mrow0 = mnew0; mrow1 = mnew1;

        float rs0 = 0.f, rs1 = 0.f;
        #pragma unroll
        for (int nf = 0; nf < 8; nf++) {
            if (nf < nf_max) {
                sc[nf][0] = ex2(sc[nf][0] - mnew0);
                sc[nf][1] = ex2(sc[nf][1] - mnew0);
                sc[nf][2] = ex2(sc[nf][2] - mnew1);
                sc[nf][3] = ex2(sc[nf][3] - mnew1);
                rs0 += sc[nf][0] + sc[nf][1];
                rs1 += sc[nf][2] + sc[nf][3];
            }
        }
        rs0 += __shfl_xor_sync(0xffffffffu, rs0, 1);
        rs0 += __shfl_xor_sync(0xffffffffu, rs0, 2);
        rs1 += __shfl_xor_sync(0xffffffffu, rs1, 1);
        rs1 += __shfl_xor_sync(0xffffffffu, rs1, 2);
        lrow0 = lrow0 * f0 + rs0;
        lrow1 = lrow1 * f1 + rs1;

        #pragma unroll
        for (int nf2 = 0; nf2 < 16; nf2++) {
            Oacc[nf2][0] *= f0; Oacc[nf2][1] *= f0;
            Oacc[nf2][2] *= f1; Oacc[nf2][3] *= f1;
        }

        // ---- O += P V (skip fully-masked k-slices) ----
        #pragma unroll
        for (int kk = 0; kk < 4; kk++) {
            if (kk < kk_max) {
                uint32_t aP[4];
                aP[0] = pack_h2(sc[2 * kk][0],     sc[2 * kk][1]);
                aP[1] = pack_h2(sc[2 * kk][2],     sc[2 * kk][3]);
                aP[2] = pack_h2(sc[2 * kk + 1][0], sc[2 * kk + 1][1]);
                aP[3] = pack_h2(sc[2 * kk + 1][2], sc[2 * kk + 1][3]);

                #pragma unroll
                for (int np = 0; np < 8; np++) {
                    int vrow = np * 16 + lhi * 8 + l7;
                    int ch   = 2 * kk + lb3;
                    uint32_t bv4[4];
                    ldsm_x4(bv4, vB + OFF128(vrow, ch));
                    mma_f16(Oacc[2 * np],     aP, &bv4[0]);
                    mma_f16(Oacc[2 * np + 1], aP, &bv4[2]);
                }
            }
        }

        __syncthreads();
    }

    const float inv0 = 1.0f / lrow0, inv1 = 1.0f / lrow1;
    const int r0 = m0 + warp * 16 + g;
    #pragma unroll
    for (int nf2 = 0; nf2 < 16; nf2++) {
        int cc = h * D_ + nf2 * 8 + 2 * t;
        __half* C0 = AO + (size_t)(b * S_ + r0) * (HQ_ * D_) + cc;
        __half* C1 = AO + (size_t)(b * S_ + r0 + 8) * (HQ_ * D_) + cc;
        *(__half2*)C0 = __floats2half2_rn(Oacc[nf2][0] * inv0, Oacc[nf2][1] * inv0);
        *(__half2*)C1 = __floats2half2_rn(Oacc[nf2][2] * inv1, Oacc[nf2][3] * inv1);
    }
}

// ---------------------------------------------------------------------------
// kernel_launch
// ---------------------------------------------------------------------------
extern "C" void kernel_launch(void* const* d_in, const int* in_sizes, int n_in,
                              void* d_out, int out_size) {
    const float* x  = (const float*)d_in[0];
    const int*   ip = (const int*)  d_in[1];
    const float* fc = (const float*)d_in[2];
    const float* wq = (const float*)d_in[3];
    const float* wk = (const float*)d_in[4];
    const float* wv = (const float*)d_in[5];
    const float* wo = (const float*)d_in[6];
    float* out = (float*)d_out;

    __half *xH, *wqT, *wkT, *wvT, *woT, *Qb, *Kc, *Vc, *AO;
    cudaGetSymbolAddress((void**)&xH,  g_xH);
    cudaGetSymbolAddress((void**)&wqT, g_wqT);
    cudaGetSymbolAddress((void**)&wkT, g_wkT);
    cudaGetSymbolAddress((void**)&wvT, g_wvT);
    cudaGetSymbolAddress((void**)&woT, g_woT);
    cudaGetSymbolAddress((void**)&Qb,  g_Qb);
    cudaGetSymbolAddress((void**)&Kc,  g_Kc);
    cudaGetSymbolAddress((void**)&Vc,  g_Vc);
    cudaGetSymbolAddress((void**)&AO,  g_AO);

    static int attr_set = 0;
    if (!attr_set) {
        cudaFuncSetAttribute(flash_f16, cudaFuncAttributeMaxDynamicSharedMemorySize, FLASH_SMEM);
        cudaFuncSetAttribute(gemm_f16<0>, cudaFuncAttributeMaxDynamicSharedMemorySize, GEMM_DSMEM);
        cudaFuncSetAttribute(gemm_f16<3>, cudaFuncAttributeMaxDynamicSharedMemorySize, GEMM_DSMEM);
        attr_set = 1;
    }

    // 0) pre-convert x (fp16); all 4 weight transposes in one launch
    const int n4_x = (M_ * E_) / 4;
    cvt_f16_arr<<<(n4_x + 255) / 256, 256>>>((const float4*)x, (uint2*)xH, n4_x);
    cvt_transpose_all<<<40960, dim3(32, 8)>>>(wq, wk, wv, wo, wqT, wkT, wvT, woT);

    // 1) Combined Q+K+V projection (one launch)
    gemm_f16<3><<<dim3(48, M_ / 128), 256, GEMM_DSMEM>>>(
        xH, wqT, wkT, wvT, nullptr, Qb, Kc, Vc, fc, ip, M_, HQ_ * D_, E_);

    // 2) Fused flash attention
    flash_f16<<<dim3(S_ / 128, B_ * HQ_), 256, FLASH_SMEM>>>(Qb, Kc, Vc, AO);

    // 3) Output projection (fp32 out)
    gemm_f16<0><<<dim3(E_ / 128, M_ / 128), 256, GEMM_DSMEM>>>(
        AO, woT, nullptr, nullptr, out, nullptr, nullptr, nullptr, nullptr, nullptr,
        M_, E_, E_);
}

// round 14
// speedup vs baseline: 1.0644x; 1.0644x over previous
#include <cuda_runtime.h>
#include <cuda_fp16.h>
#include <float.h>
#include <math.h>
#include <stdint.h>

// Problem constants
#define B_   2
#define S_   2048
#define E_   4096
#define HQ_  32
#define HKV_ 8
#define D_   128
#define M_   (B_ * S_)          // 4096
#define SCALE_ 0.015625f        // 1/sqrt(4096)
#define LOG2E_ 1.44269504088896f

// ---------------------------------------------------------------------------
// Scratch
// ---------------------------------------------------------------------------
__device__ __half g_xH [(size_t)M_ * E_];             // x fp16 [M][K]
__device__ __half g_wqT[(size_t)(HQ_ * D_) * E_];     // wq^T [N][K]
__device__ __half g_wkT[(size_t)(HKV_ * D_) * E_];    // wk^T
__device__ __half g_wvT[(size_t)(HKV_ * D_) * E_];    // wv^T
__device__ __half g_woT[(size_t)E_ * (HQ_ * D_)];     // wo^T
__device__ __half g_Qb [(size_t)B_ * HQ_ * S_ * D_];  // roped+scaled(log2e) Q [b,h,s,d]
__device__ __half g_Kc [(size_t)B_ * HKV_ * S_ * D_]; // roped K cache   [b,h,pos,d]
__device__ __half g_Vc [(size_t)B_ * HKV_ * D_ * S_]; // V cache transposed [b,h,d,pos]
__device__ __half g_AO [(size_t)M_ * (HQ_ * D_)];     // attn out fp16

// ---------------------------------------------------------------------------
// helpers
// ---------------------------------------------------------------------------
__device__ __forceinline__ void mma_f16(float* c, const uint32_t* a, const uint32_t* b) {
    asm volatile(
        "mma.sync.aligned.m16n8k16.row.col.f32.f16.f16.f32 "
        "{%0,%1,%2,%3},{%4,%5,%6,%7},{%8,%9},{%0,%1,%2,%3};"
        : "+f"(c[0]), "+f"(c[1]), "+f"(c[2]), "+f"(c[3])
        : "r"(a[0]), "r"(a[1]), "r"(a[2]), "r"(a[3]), "r"(b[0]), "r"(b[1]));
}
__device__ __forceinline__ void ldsm_x4(uint32_t* r, uint32_t addr) {
    asm volatile("ldmatrix.sync.aligned.m8n8.x4.shared.b16 {%0,%1,%2,%3}, [%4];"
        : "=r"(r[0]), "=r"(r[1]), "=r"(r[2]), "=r"(r[3]) : "r"(addr));
}
__device__ __forceinline__ void cp16s(uint32_t saddr, const void* gmem) {
    asm volatile("cp.async.cg.shared.global [%0], [%1], 16;\n" :: "r"(saddr), "l"(gmem));
}
#define CP_COMMIT() asm volatile("cp.async.commit_group;\n" ::: "memory")
#define CP_WAIT(n)  asm volatile("cp.async.wait_group %0;\n" :: "n"(n) : "memory")
__device__ __forceinline__ uint32_t smem_u32(const void* p) {
    return (uint32_t)__cvta_generic_to_shared(p);
}
__device__ __forceinline__ uint32_t pack_h2(float a, float b) {
    __half2 h = __floats2half2_rn(a, b);
    return *(uint32_t*)&h;
}
__device__ __forceinline__ float ex2(float x) {
    float y;
    asm("ex2.approx.ftz.f32 %0, %1;" : "=f"(y) : "f"(x));
    return y;
}
// swizzled byte offsets (cp = 16B-chunk index within row)
#define OFF256(row, cp) ((uint32_t)((row) * 256 + (((((cp) & 7) ^ ((row) & 7)) | ((cp) & 8)) << 4)))
#define OFF128(row, cp) ((uint32_t)((row) * 128 + ((((cp) ^ ((row) & 7))) << 4)))

// ---------------------------------------------------------------------------
// Pre-pass: fp32 -> fp16 (+ transpose for weights)
// ---------------------------------------------------------------------------
__global__ void cvt_f16_arr(const float4* __restrict__ in, uint2* __restrict__ out, int n4) {
    int i = blockIdx.x * 256 + threadIdx.x;
    if (i < n4) {
        float4 v = in[i];
        out[i] = make_uint2(pack_h2(v.x, v.y), pack_h2(v.z, v.w));
    }
}
__global__ void cvt_transpose_h(const float* __restrict__ in, __half* __restrict__ out,
                                int Kd, int Nd) {
    __shared__ __half t[32][33];
    int bx = blockIdx.x * 32, by = blockIdx.y * 32;
    int x = threadIdx.x, y = threadIdx.y;
    #pragma unroll
    for (int j = 0; j < 32; j += 8)
        t[y + j][x] = __float2half(in[(size_t)(by + y + j) * Nd + bx + x]);
    __syncthreads();
    #pragma unroll
    for (int j = 0; j < 32; j += 8)
        out[(size_t)(bx + y + j) * Kd + by + x] = t[x][y + j];
}

// ---------------------------------------------------------------------------
// fp16 GEMM: 128x128 CTA tile, 8 warps (2m x 4n, 64x32 warp tile), KC=64,
// 3-stage cp.async ring, ldmatrix fragments, 2 CTAs/SM.
//   MODE 0: fp32 C out (out-projection)
//   MODE 3: combined QKV projection: bx<32 Q | bx<40 K | else V
// ---------------------------------------------------------------------------
#define KCH 64
#define TILEB (128 * 128)            // 16KB per operand tile
#define NSTG 3
#define GEMM_DSMEM (NSTG * 2 * TILEB)   // 96KB

template<int MODE>
__global__ __launch_bounds__(256, 2) void gemm_f16(
    const __half* __restrict__ A, const __half* __restrict__ Bq,
    const __half* __restrict__ Bk, const __half* __restrict__ Bv,
    float* __restrict__ C, __half* __restrict__ Oq, __half* __restrict__ Okk,
    __half* __restrict__ Ov,
    const float* __restrict__ fc, const int* __restrict__ ip,
    int M, int N, int K)
{
    extern __shared__ __align__(128) uint8_t dynraw[];
    const uint32_t smBase = smem_u32(dynraw);

    const int tid = threadIdx.x;
    const int lane = tid & 31, warp = tid >> 5;
    const int g = lane >> 2, t = lane & 3;
    const int wm = warp & 1, wn = warp >> 1;
    const int m0 = blockIdx.y * 128;

    const int l7 = lane & 7, l15 = lane & 15;
    const int lhi = lane >> 4, lb3 = (lane >> 3) & 1;

    const __half* Bt;
    int n0;
    int kind = 0;   // 0=Q(or MODE0), 1=K, 2=V
    if (MODE == 3) {
        if (blockIdx.x < 32)      { Bt = Bq; n0 = blockIdx.x * 128;        kind = 0; }
        else if (blockIdx.x < 40) { Bt = Bk; n0 = (blockIdx.x - 32) * 128; kind = 1; }
        else                      { Bt = Bv; n0 = (blockIdx.x - 40) * 128; kind = 2; }
    } else {
        Bt = Bq; n0 = blockIdx.x * 128;
    }

    float acc[4][4][4] = {};

    auto load_chunk = [&](int ck, int st) {
        const uint32_t aB = smBase + st * TILEB;
        const uint32_t bB = smBase + NSTG * TILEB + st * TILEB;
        #pragma unroll
        for (int i = 0; i < 4; i++) {
            int c = i * 256 + tid;
            int row = c >> 3, cp = c & 7;
            uint32_t off = OFF128(row, cp);
            cp16s(aB + off, A  + (size_t)(m0 + row) * K + ck * KCH + cp * 8);
            cp16s(bB + off, Bt + (size_t)(n0 + row) * K + ck * KCH + cp * 8);
        }
        CP_COMMIT();
    };

    const int nchunk = K / KCH;
    load_chunk(0, 0);
    load_chunk(1, 1);

    for (int ci = 0; ci < nchunk; ci++) {
        const int s = ci % NSTG;
        if (ci + 1 < nchunk) { CP_WAIT(1); } else { CP_WAIT(0); }
        __syncthreads();
        if (ci + 2 < nchunk) load_chunk(ci + 2, (ci + 2) % NSTG);

        const uint32_t aB = smBase + s * TILEB;
        const uint32_t bB = smBase + NSTG * TILEB + s * TILEB;

        #pragma unroll
        for (int kk = 0; kk < 4; kk++) {
            uint32_t af[4][4], bf[2][4];
            #pragma unroll
            for (int mt = 0; mt < 4; mt++) {
                int row = wm * 64 + mt * 16 + l15;
                int ch  = 2 * kk + lhi;
                ldsm_x4(af[mt], aB + OFF128(row, ch));
            }
            #pragma unroll
            for (int p = 0; p < 2; p++) {
                int row = wn * 32 + p * 16 + lhi * 8 + l7;
                int ch  = 2 * kk + lb3;
                ldsm_x4(bf[p], bB + OFF128(row, ch));
            }
            #pragma unroll
            for (int mt = 0; mt < 4; mt++) {
                #pragma unroll
                for (int p = 0; p < 2; p++) {
                    mma_f16(acc[mt][2 * p],     af[mt], &bf[p][0]);
                    mma_f16(acc[mt][2 * p + 1], af[mt], &bf[p][2]);
                }
            }
        }
    }
    __syncthreads();

    if (MODE == 0) {
        #pragma unroll
        for (int mt = 0; mt < 4; mt++) {
            int r = m0 + wm * 64 + mt * 16 + g;
            #pragma unroll
            for (int nt = 0; nt < 4; nt++) {
                int cc = n0 + wn * 32 + nt * 8 + t * 2;
                *(float2*)(C + (size_t)r * N + cc)       = make_float2(acc[mt][nt][0], acc[mt][nt][1]);
                *(float2*)(C + (size_t)(r + 8) * N + cc) = make_float2(acc[mt][nt][2], acc[mt][nt][3]);
            }
        }
    } else {
        const bool doRope = (kind != 2);
        #pragma unroll
        for (int mt = 0; mt < 4; mt++) {
            int r = m0 + wm * 64 + mt * 16 + g;
            int b = r >> 11;
            int sA = r & (S_ - 1);
            int sB = sA + 8;
            #pragma unroll
            for (int nt = 0; nt < 4; nt++) {
                int cc = n0 + wn * 32 + nt * 8 + t * 2;
                int h  = cc >> 7;
                int dd = cc & (D_ - 1);
                int p  = dd >> 1;

                float a0 = acc[mt][nt][0], a1 = acc[mt][nt][1];
                float a2 = acc[mt][nt][2], a3 = acc[mt][nt][3];
                float o0, o1, o2, o3;
                if (doRope) {
                    float2 csA = ((const float2*)fc)[(size_t)sA * 64 + p];
                    float2 csB = ((const float2*)fc)[(size_t)sB * 64 + p];
                    o0 = a0 * csA.x - a1 * csA.y;
                    o1 = a0 * csA.y + a1 * csA.x;
                    o2 = a2 * csB.x - a3 * csB.y;
                    o3 = a2 * csB.y + a3 * csB.x;
                } else {
                    o0 = a0; o1 = a1; o2 = a2; o3 = a3;
                }

                if (kind == 0) {
                    // scale includes log2e for exp2-domain softmax
                    const float sc2 = SCALE_ * LOG2E_;
                    o0 *= sc2; o1 *= sc2; o2 *= sc2; o3 *= sc2;
                    *(__half2*)(Oq + ((size_t)(b * HQ_ + h) * S_ + sA) * D_ + dd) = __floats2half2_rn(o0, o1);
                    *(__half2*)(Oq + ((size_t)(b * HQ_ + h) * S_ + sB) * D_ + dd) = __floats2half2_rn(o2, o3);
                } else if (kind == 1) {
                    int posA = ip[sA], posB = ip[sB];
                    *(__half2*)(Okk + ((size_t)(b * HKV_ + h) * S_ + posA) * D_ + dd) = __floats2half2_rn(o0, o1);
                    *(__half2*)(Okk + ((size_t)(b * HKV_ + h) * S_ + posB) * D_ + dd) = __floats2half2_rn(o2, o3);
                } else {
                    int posA = ip[sA], posB = ip[sB];
                    size_t base = (size_t)(b * HKV_ + h) * D_;
                    Ov[(base + dd)     * S_ + posA] = __float2half(o0);
                    Ov[(base + dd + 1) * S_ + posA] = __float2half(o1);
                    Ov[(base + dd)     * S_ + posB] = __float2half(o2);
                    Ov[(base + dd + 1) * S_ + posB] = __float2half(o3);
                }
            }
        }
    }
}

// ---------------------------------------------------------------------------
// Fused flash attention (R12 structure; exp2-domain softmax)
// ---------------------------------------------------------------------------
#define SMQ_OFF  0
#define SMK_OFF  32768
#define SMV_OFF  (32768 + 2 * 16384)
#define FLASH_SMEM (32768 + 4 * 16384)

__device__ __forceinline__ void fa_load_kv_h(
    uint32_t smBase, int stage,
    const __half* __restrict__ Kp, const __half* __restrict__ Vtp,
    int kcol0, int tid)
{
    const uint32_t kB = smBase + SMK_OFF + stage * 16384;
    const uint32_t vB = smBase + SMV_OFF + stage * 16384;
    #pragma unroll
    for (int i = 0; i < 4; i++) {
        int c = i * 256 + tid;
        {
            int row = c >> 4, cp = c & 15;
            cp16s(kB + OFF256(row, cp), Kp + (size_t)row * D_ + cp * 8);
        }
        {
            int row = c >> 3, cp = c & 7;
            cp16s(vB + OFF128(row, cp), Vtp + (size_t)row * S_ + kcol0 + cp * 8);
        }
    }
    CP_COMMIT();
}

__global__ __launch_bounds__(256, 1) void flash_f16(
    const __half* __restrict__ Qb, const __half* __restrict__ Kc,
    const __half* __restrict__ Vc, __half* __restrict__ AO)
{
    extern __shared__ __align__(128) uint8_t smraw[];
    const uint32_t smBase = smem_u32(smraw);

    const int qt = (S_ / 128 - 1) - blockIdx.x;
    const int bh = blockIdx.y;
    const int b = bh / HQ_, h = bh % HQ_;
    const int kvh = h / (HQ_ / HKV_);
    const int m0 = qt * 128;

    const int tid = threadIdx.x, lane = tid & 31, warp = tid >> 5;
    const int g = lane >> 2, t = lane & 3;
    const int l7 = lane & 7, lhi = lane >> 4, lb3 = (lane >> 3) & 1;

    const __half* Qbase = Qb + (size_t)(b * HQ_ + h) * S_ * D_ + (size_t)m0 * D_;
    const __half* Kbase = Kc + (size_t)(b * HKV_ + kvh) * S_ * D_;
    const __half* Vtb   = Vc + (size_t)(b * HKV_ + kvh) * D_ * S_;

    #pragma unroll
    for (int i = 0; i < 8; i++) {
        int c = i * 256 + tid;
        int row = c >> 4, cp = c & 15;
        cp16s(smBase + SMQ_OFF + OFF256(row, cp), Qbase + (size_t)row * D_ + cp * 8);
    }
    CP_COMMIT();

    const int nkt = 2 * qt + 2;
    fa_load_kv_h(smBase, 0, Kbase, Vtb, 0, tid);

    uint32_t qf[8][4];
    float Oacc[16][4] = {};
    float mrow0 = -FLT_MAX, mrow1 = -FLT_MAX;
    float lrow0 = 0.f, lrow1 = 0.f;

    for (int kt = 0; kt < nkt; kt++) {
        const int s = kt & 1;
        if (kt + 1 < nkt) {
            fa_load_kv_h(smBase, s ^ 1, Kbase + (size_t)(kt + 1) * 64 * D_,
                         Vtb, (kt + 1) * 64, tid);
            CP_WAIT(1);
        } else {
            CP_WAIT(0);
        }
        __syncthreads();

        if (kt == 0) {
            const int qrow = warp * 16 + (lane & 15);
            #pragma unroll
            for (int ks = 0; ks < 8; ks++) {
                int ch = 2 * ks + lhi;
                ldsm_x4(qf[ks], smBase + SMQ_OFF + OFF256(qrow, ch));
            }
        }

        const uint32_t kB = smBase + SMK_OFF + s * 16384;
        const uint32_t vB = smBase + SMV_OFF + s * 16384;

        float sc[8][4];
        #pragma unroll
        for (int nf = 0; nf < 8; nf++)
            sc[nf][0] = sc[nf][1] = sc[nf][2] = sc[nf][3] = 0.f;
        #pragma unroll
        for (int ks = 0; ks < 8; ks++) {
            #pragma unroll
            for (int nfp = 0; nfp < 4; nfp++) {
                int krow = nfp * 16 + lhi * 8 + l7;
                int ch   = 2 * ks + lb3;
                uint32_t bb[4];
                ldsm_x4(bb, kB + OFF256(krow, ch));
                mma_f16(sc[2 * nfp],     qf[ks], &bb[0]);
                mma_f16(sc[2 * nfp + 1], qf[ks], &bb[2]);
            }
        }

        const int r0 = m0 + warp * 16 + g;
        const int r1 = r0 + 8;
        if (kt >= 2 * qt) {
            #pragma unroll
            for (int nf = 0; nf < 8; nf++) {
                int c0 = kt * 64 + nf * 8 + 2 * t;
                if (c0     > r0) sc[nf][0] = -FLT_MAX;
                if (c0 + 1 > r0) sc[nf][1] = -FLT_MAX;
                if (c0     > r1) sc[nf][2] = -FLT_MAX;
                if (c0 + 1 > r1) sc[nf][3] = -FLT_MAX;
            }
        }

        float mx0 = -FLT_MAX, mx1 = -FLT_MAX;
        #pragma unroll
        for (int nf = 0; nf < 8; nf++) {
            mx0 = fmaxf(mx0, fmaxf(sc[nf][0], sc[nf][1]));
            mx1 = fmaxf(mx1, fmaxf(sc[nf][2], sc[nf][3]));
        }
        mx0 = fmaxf(mx0, __shfl_xor_sync(0xffffffffu, mx0, 1));
        mx0 = fmaxf(mx0, __shfl_xor_sync(0xffffffffu, mx0, 2));
        mx1 = fmaxf(mx1, __shfl_xor_sync(0xffffffffu, mx1, 1));
        mx1 = fmaxf(mx1, __shfl_xor_sync(0xffffffffu, mx1, 2));

        float mnew0 = fmaxf(mrow0, mx0), mnew1 = fmaxf(mrow1, mx1);
        float f0 = ex2(mrow0 - mnew0), f1 = ex2(mrow1 - mnew1);
        mrow0 = mnew0; mrow1 = mnew1;

        float rs0 = 0.f, rs1 = 0.f;
        #pragma unroll
        for (int nf = 0; nf < 8; nf++) {
            sc[nf][0] = ex2(sc[nf][0] - mnew0);
            sc[nf][1] = ex2(sc[nf][1] - mnew0);
            sc[nf][2] = ex2(sc[nf][2] - mnew1);
            sc[nf][3] = ex2(sc[nf][3] - mnew1);
            rs0 += sc[nf][0] + sc[nf][1];
            rs1 += sc[nf][2] + sc[nf][3];
        }
        rs0 += __shfl_xor_sync(0xffffffffu, rs0, 1);
        rs0 += __shfl_xor_sync(0xffffffffu, rs0, 2);
        rs1 += __shfl_xor_sync(0xffffffffu, rs1, 1);
        rs1 += __shfl_xor_sync(0xffffffffu, rs1, 2);
        lrow0 = lrow0 * f0 + rs0;
        lrow1 = lrow1 * f1 + rs1;

        #pragma unroll
        for (int nf2 = 0; nf2 < 16; nf2++) {
            Oacc[nf2][0] *= f0; Oacc[nf2][1] *= f0;
            Oacc[nf2][2] *= f1; Oacc[nf2][3] *= f1;
        }

        #pragma unroll
        for (int kk = 0; kk < 4; kk++) {
            uint32_t aP[4];
            aP[0] = pack_h2(sc[2 * kk][0],     sc[2 * kk][1]);
            aP[1] = pack_h2(sc[2 * kk][2],     sc[2 * kk][3]);
            aP[2] = pack_h2(sc[2 * kk + 1][0], sc[2 * kk + 1][1]);
            aP[3] = pack_h2(sc[2 * kk + 1][2], sc[2 * kk + 1][3]);

            #pragma unroll
            for (int np = 0; np < 8; np++) {
                int vrow = np * 16 + lhi * 8 + l7;
                int ch   = 2 * kk + lb3;
                uint32_t bv4[4];
                ldsm_x4(bv4, vB + OFF128(vrow, ch));
                mma_f16(Oacc[2 * np],     aP, &bv4[0]);
                mma_f16(Oacc[2 * np + 1], aP, &bv4[2]);
            }
        }

        __syncthreads();
    }

    const float inv0 = 1.0f / lrow0, inv1 = 1.0f / lrow1;
    const int r0 = m0 + warp * 16 + g;
    #pragma unroll
    for (int nf2 = 0; nf2 < 16; nf2++) {
        int cc = h * D_ + nf2 * 8 + 2 * t;
        __half* C0 = AO + (size_t)(b * S_ + r0) * (HQ_ * D_) + cc;
        __half* C1 = AO + (size_t)(b * S_ + r0 + 8) * (HQ_ * D_) + cc;
        *(__half2*)C0 = __floats2half2_rn(Oacc[nf2][0] * inv0, Oacc[nf2][1] * inv0);
        *(__half2*)C1 = __floats2half2_rn(Oacc[nf2][2] * inv1, Oacc[nf2][3] * inv1);
    }
}

// ---------------------------------------------------------------------------
// kernel_launch
// ---------------------------------------------------------------------------
extern "C" void kernel_launch(void* const* d_in, const int* in_sizes, int n_in,
                              void* d_out, int out_size) {
    const float* x  = (const float*)d_in[0];
    const int*   ip = (const int*)  d_in[1];
    const float* fc = (const float*)d_in[2];
    const float* wq = (const float*)d_in[3];
    const float* wk = (const float*)d_in[4];
    const float* wv = (const float*)d_in[5];
    const float* wo = (const float*)d_in[6];
    float* out = (float*)d_out;

    __half *xH, *wqT, *wkT, *wvT, *woT, *Qb, *Kc, *Vc, *AO;
    cudaGetSymbolAddress((void**)&xH,  g_xH);
    cudaGetSymbolAddress((void**)&wqT, g_wqT);
    cudaGetSymbolAddress((void**)&wkT, g_wkT);
    cudaGetSymbolAddress((void**)&wvT, g_wvT);
    cudaGetSymbolAddress((void**)&woT, g_woT);
    cudaGetSymbolAddress((void**)&Qb,  g_Qb);
    cudaGetSymbolAddress((void**)&Kc,  g_Kc);
    cudaGetSymbolAddress((void**)&Vc,  g_Vc);
    cudaGetSymbolAddress((void**)&AO,  g_AO);

    static int attr_set = 0;
    if (!attr_set) {
        cudaFuncSetAttribute(flash_f16, cudaFuncAttributeMaxDynamicSharedMemorySize, FLASH_SMEM);
        cudaFuncSetAttribute(gemm_f16<0>, cudaFuncAttributeMaxDynamicSharedMemorySize, GEMM_DSMEM);
        cudaFuncSetAttribute(gemm_f16<3>, cudaFuncAttributeMaxDynamicSharedMemorySize, GEMM_DSMEM);
        attr_set = 1;
    }

    // 0) pre-convert x (fp16), transpose+convert weights (fp16 [N][K])
    const int n4_x = (M_ * E_) / 4;
    cvt_f16_arr<<<(n4_x + 255) / 256, 256>>>((const float4*)x, (uint2*)xH, n4_x);
    cvt_transpose_h<<<dim3((HQ_ * D_) / 32, E_ / 32), dim3(32, 8)>>>(wq, wqT, E_, HQ_ * D_);
    cvt_transpose_h<<<dim3((HKV_ * D_) / 32, E_ / 32), dim3(32, 8)>>>(wk, wkT, E_, HKV_ * D_);
    cvt_transpose_h<<<dim3((HKV_ * D_) / 32, E_ / 32), dim3(32, 8)>>>(wv, wvT, E_, HKV_ * D_);
    cvt_transpose_h<<<dim3(E_ / 32, (HQ_ * D_) / 32), dim3(32, 8)>>>(wo, woT, HQ_ * D_, E_);

    // 1) Combined Q+K+V projection (one launch; Q/K/V by blockIdx.x)
    gemm_f16<3><<<dim3(48, M_ / 128), 256, GEMM_DSMEM>>>(
        xH, wqT, wkT, wvT, nullptr, Qb, Kc, Vc, fc, ip, M_, HQ_ * D_, E_);

    // 2) Fused flash attention
    flash_f16<<<dim3(S_ / 128, B_ * HQ_), 256, FLASH_SMEM>>>(Qb, Kc, Vc, AO);

    // 3) Output projection (fp32 out)
    gemm_f16<0><<<dim3(E_ / 128, M_ / 128), 256, GEMM_DSMEM>>>(
        AO, woT, nullptr, nullptr, out, nullptr, nullptr, nullptr, nullptr, nullptr,
        M_, E_, E_);
}

// round 15
// speedup vs baseline: 1.0679x; 1.0033x over previous
#include <cuda_runtime.h>
#include <cuda_fp16.h>
#include <float.h>
#include <math.h>
#include <stdint.h>

// Problem constants
#define B_   2
#define S_   2048
#define E_   4096
#define HQ_  32
#define HKV_ 8
#define D_   128
#define M_   (B_ * S_)          // 4096
#define SCALE_ 0.015625f        // 1/sqrt(4096)
#define LOG2E_ 1.44269504088896f

// ---------------------------------------------------------------------------
// Scratch
// ---------------------------------------------------------------------------
__device__ __half g_xH [(size_t)M_ * E_];             // x fp16 [M][K]
__device__ __half g_wqT[(size_t)(HQ_ * D_) * E_];     // wq^T [N][K]
__device__ __half g_wkT[(size_t)(HKV_ * D_) * E_];    // wk^T
__device__ __half g_wvT[(size_t)(HKV_ * D_) * E_];    // wv^T
__device__ __half g_woT[(size_t)E_ * (HQ_ * D_)];     // wo^T
__device__ __half g_Qb [(size_t)B_ * HQ_ * S_ * D_];  // roped+scaled(log2e) Q [b,h,s,d]
__device__ __half g_Kc [(size_t)B_ * HKV_ * S_ * D_]; // roped K cache   [b,h,pos,d]
__device__ __half g_Vc [(size_t)B_ * HKV_ * D_ * S_]; // V cache transposed [b,h,d,pos]
__device__ __half g_AO [(size_t)M_ * (HQ_ * D_)];     // attn out fp16

// ---------------------------------------------------------------------------
// helpers
// ---------------------------------------------------------------------------
__device__ __forceinline__ void mma_f16(float* c, const uint32_t* a, const uint32_t* b) {
    asm volatile(
        "mma.sync.aligned.m16n8k16.row.col.f32.f16.f16.f32 "
        "{%0,%1,%2,%3},{%4,%5,%6,%7},{%8,%9},{%0,%1,%2,%3};"
        : "+f"(c[0]), "+f"(c[1]), "+f"(c[2]), "+f"(c[3])
        : "r"(a[0]), "r"(a[1]), "r"(a[2]), "r"(a[3]), "r"(b[0]), "r"(b[1]));
}
__device__ __forceinline__ void ldsm_x4(uint32_t* r, uint32_t addr) {
    asm volatile("ldmatrix.sync.aligned.m8n8.x4.shared.b16 {%0,%1,%2,%3}, [%4];"
        : "=r"(r[0]), "=r"(r[1]), "=r"(r[2]), "=r"(r[3]) : "r"(addr));
}
__device__ __forceinline__ void cp16s(uint32_t saddr, const void* gmem) {
    asm volatile("cp.async.cg.shared.global [%0], [%1], 16;\n" :: "r"(saddr), "l"(gmem));
}
#define CP_COMMIT() asm volatile("cp.async.commit_group;\n" ::: "memory")
#define CP_WAIT(n)  asm volatile("cp.async.wait_group %0;\n" :: "n"(n) : "memory")
__device__ __forceinline__ uint32_t smem_u32(const void* p) {
    return (uint32_t)__cvta_generic_to_shared(p);
}
__device__ __forceinline__ uint32_t pack_h2(float a, float b) {
    __half2 h = __floats2half2_rn(a, b);
    return *(uint32_t*)&h;
}
__device__ __forceinline__ float ex2(float x) {
    float y;
    asm("ex2.approx.ftz.f32 %0, %1;" : "=f"(y) : "f"(x));
    return y;
}
// swizzled byte offsets (cp = 16B-chunk index within row)
#define OFF256(row, cp) ((uint32_t)((row) * 256 + (((((cp) & 7) ^ ((row) & 7)) | ((cp) & 8)) << 4)))
#define OFF128(row, cp) ((uint32_t)((row) * 128 + ((((cp) ^ ((row) & 7))) << 4)))

// ---------------------------------------------------------------------------
// Pre-pass: fp32 -> fp16 conversion of x; all 4 weight transposes in 1 launch
// ---------------------------------------------------------------------------
__global__ void cvt_f16_arr(const float4* __restrict__ in, uint2* __restrict__ out, int n4) {
    int i = blockIdx.x * 256 + threadIdx.x;
    if (i < n4) {
        float4 v = in[i];
        out[i] = make_uint2(pack_h2(v.x, v.y), pack_h2(v.z, v.w));
    }
}
// blocks [0,16384): wq | [16384,20480): wk | [20480,24576): wv | [24576,40960): wo
__global__ void cvt_transpose_all(
    const float* __restrict__ wq, const float* __restrict__ wk,
    const float* __restrict__ wv, const float* __restrict__ wo,
    __half* __restrict__ oq, __half* __restrict__ ok,
    __half* __restrict__ ov, __half* __restrict__ oo)
{
    __shared__ __half tb[32][33];
    const int bid = blockIdx.x;
    const float* in;
    __half* out;
    int Kd, Nd, bx, by;
    if (bid < 16384)      { in = wq; out = oq; Kd = E_; Nd = HQ_ * D_;
                            int r = bid;          bx = (r & 127) * 32; by = (r >> 7) * 32; }
    else if (bid < 20480) { in = wk; out = ok; Kd = E_; Nd = HKV_ * D_;
                            int r = bid - 16384;  bx = (r & 31) * 32;  by = (r >> 5) * 32; }
    else if (bid < 24576) { in = wv; out = ov; Kd = E_; Nd = HKV_ * D_;
                            int r = bid - 20480;  bx = (r & 31) * 32;  by = (r >> 5) * 32; }
    else                  { in = wo; out = oo; Kd = HQ_ * D_; Nd = E_;
                            int r = bid - 24576;  bx = (r & 127) * 32; by = (r >> 7) * 32; }
    const int x = threadIdx.x, y = threadIdx.y;   // block (32, 8)
    #pragma unroll
    for (int j = 0; j < 32; j += 8)
        tb[y + j][x] = __float2half(in[(size_t)(by + y + j) * Nd + bx + x]);
    __syncthreads();
    #pragma unroll
    for (int j = 0; j < 32; j += 8)
        out[(size_t)(bx + y + j) * Kd + by + x] = tb[x][y + j];
}

// ---------------------------------------------------------------------------
// fp16 GEMM: 128x128 CTA tile, 8 warps (2m x 4n), KC=64, 3-stage ring,
// ldmatrix fragments, 2 CTAs/SM. (R12/R14 structure, unchanged)
//   MODE 0: fp32 C out (out-projection)
//   MODE 3: combined QKV projection: bx<32 Q | bx<40 K | else V
// ---------------------------------------------------------------------------
#define KCH 64
#define TILEB (128 * 128)
#define NSTG 3
#define GEMM_DSMEM (NSTG * 2 * TILEB)   // 96KB

template<int MODE>
__global__ __launch_bounds__(256, 2) void gemm_f16(
    const __half* __restrict__ A, const __half* __restrict__ Bq,
    const __half* __restrict__ Bk, const __half* __restrict__ Bv,
    float* __restrict__ C, __half* __restrict__ Oq, __half* __restrict__ Okk,
    __half* __restrict__ Ov,
    const float* __restrict__ fc, const int* __restrict__ ip,
    int M, int N, int K)
{
    extern __shared__ __align__(128) uint8_t dynraw[];
    const uint32_t smBase = smem_u32(dynraw);

    const int tid = threadIdx.x;
    const int lane = tid & 31, warp = tid >> 5;
    const int g = lane >> 2, t = lane & 3;
    const int wm = warp & 1, wn = warp >> 1;
    const int m0 = blockIdx.y * 128;

    const int l7 = lane & 7, l15 = lane & 15;
    const int lhi = lane >> 4, lb3 = (lane >> 3) & 1;

    const __half* Bt;
    int n0;
    int kind = 0;
    if (MODE == 3) {
        if (blockIdx.x < 32)      { Bt = Bq; n0 = blockIdx.x * 128;        kind = 0; }
        else if (blockIdx.x < 40) { Bt = Bk; n0 = (blockIdx.x - 32) * 128; kind = 1; }
        else                      { Bt = Bv; n0 = (blockIdx.x - 40) * 128; kind = 2; }
    } else {
        Bt = Bq; n0 = blockIdx.x * 128;
    }

    float acc[4][4][4] = {};

    auto load_chunk = [&](int ck, int st) {
        const uint32_t aB = smBase + st * TILEB;
        const uint32_t bB = smBase + NSTG * TILEB + st * TILEB;
        #pragma unroll
        for (int i = 0; i < 4; i++) {
            int c = i * 256 + tid;
            int row = c >> 3, cp = c & 7;
            uint32_t off = OFF128(row, cp);
            cp16s(aB + off, A  + (size_t)(m0 + row) * K + ck * KCH + cp * 8);
            cp16s(bB + off, Bt + (size_t)(n0 + row) * K + ck * KCH + cp * 8);
        }
        CP_COMMIT();
    };

    const int nchunk = K / KCH;
    load_chunk(0, 0);
    load_chunk(1, 1);

    for (int ci = 0; ci < nchunk; ci++) {
        const int s = ci % NSTG;
        if (ci + 1 < nchunk) { CP_WAIT(1); } else { CP_WAIT(0); }
        __syncthreads();
        if (ci + 2 < nchunk) load_chunk(ci + 2, (ci + 2) % NSTG);

        const uint32_t aB = smBase + s * TILEB;
        const uint32_t bB = smBase + NSTG * TILEB + s * TILEB;

        #pragma unroll
        for (int kk = 0; kk < 4; kk++) {
            uint32_t af[4][4], bf[2][4];
            #pragma unroll
            for (int mt = 0; mt < 4; mt++) {
                int row = wm * 64 + mt * 16 + l15;
                int ch  = 2 * kk + lhi;
                ldsm_x4(af[mt], aB + OFF128(row, ch));
            }
            #pragma unroll
            for (int p = 0; p < 2; p++) {
                int row = wn * 32 + p * 16 + lhi * 8 + l7;
                int ch  = 2 * kk + lb3;
                ldsm_x4(bf[p], bB + OFF128(row, ch));
            }
            #pragma unroll
            for (int mt = 0; mt < 4; mt++) {
                #pragma unroll
                for (int p = 0; p < 2; p++) {
                    mma_f16(acc[mt][2 * p],     af[mt], &bf[p][0]);
                    mma_f16(acc[mt][2 * p + 1], af[mt], &bf[p][2]);
                }
            }
        }
    }
    __syncthreads();

    if (MODE == 0) {
        #pragma unroll
        for (int mt = 0; mt < 4; mt++) {
            int r = m0 + wm * 64 + mt * 16 + g;
            #pragma unroll
            for (int nt = 0; nt < 4; nt++) {
                int cc = n0 + wn * 32 + nt * 8 + t * 2;
                *(float2*)(C + (size_t)r * N + cc)       = make_float2(acc[mt][nt][0], acc[mt][nt][1]);
                *(float2*)(C + (size_t)(r + 8) * N + cc) = make_float2(acc[mt][nt][2], acc[mt][nt][3]);
            }
        }
    } else {
        const bool doRope = (kind != 2);
        #pragma unroll
        for (int mt = 0; mt < 4; mt++) {
            int r = m0 + wm * 64 + mt * 16 + g;
            int b = r >> 11;
            int sA = r & (S_ - 1);
            int sB = sA + 8;
            #pragma unroll
            for (int nt = 0; nt < 4; nt++) {
                int cc = n0 + wn * 32 + nt * 8 + t * 2;
                int h  = cc >> 7;
                int dd = cc & (D_ - 1);
                int p  = dd >> 1;

                float a0 = acc[mt][nt][0], a1 = acc[mt][nt][1];
                float a2 = acc[mt][nt][2], a3 = acc[mt][nt][3];
                float o0, o1, o2, o3;
                if (doRope) {
                    float2 csA = ((const float2*)fc)[(size_t)sA * 64 + p];
                    float2 csB = ((const float2*)fc)[(size_t)sB * 64 + p];
                    o0 = a0 * csA.x - a1 * csA.y;
                    o1 = a0 * csA.y + a1 * csA.x;
                    o2 = a2 * csB.x - a3 * csB.y;
                    o3 = a2 * csB.y + a3 * csB.x;
                } else {
                    o0 = a0; o1 = a1; o2 = a2; o3 = a3;
                }

                if (kind == 0) {
                    const float sc2 = SCALE_ * LOG2E_;
                    o0 *= sc2; o1 *= sc2; o2 *= sc2; o3 *= sc2;
                    *(__half2*)(Oq + ((size_t)(b * HQ_ + h) * S_ + sA) * D_ + dd) = __floats2half2_rn(o0, o1);
                    *(__half2*)(Oq + ((size_t)(b * HQ_ + h) * S_ + sB) * D_ + dd) = __floats2half2_rn(o2, o3);
                } else if (kind == 1) {
                    int posA = ip[sA], posB = ip[sB];
                    *(__half2*)(Okk + ((size_t)(b * HKV_ + h) * S_ + posA) * D_ + dd) = __floats2half2_rn(o0, o1);
                    *(__half2*)(Okk + ((size_t)(b * HKV_ + h) * S_ + posB) * D_ + dd) = __floats2half2_rn(o2, o3);
                } else {
                    int posA = ip[sA], posB = ip[sB];
                    size_t base = (size_t)(b * HKV_ + h) * D_;
                    Ov[(base + dd)     * S_ + posA] = __float2half(o0);
                    Ov[(base + dd + 1) * S_ + posA] = __float2half(o1);
                    Ov[(base + dd)     * S_ + posB] = __float2half(o2);
                    Ov[(base + dd + 1) * S_ + posB] = __float2half(o3);
                }
            }
        }
    }
}

// ---------------------------------------------------------------------------
// Fused flash attention: exp2 softmax, 3-stage KV ring, ONE barrier per kt.
// ---------------------------------------------------------------------------
#define SMQ_OFF   0
#define FKV_STG   32768                 // K(16KB)+V(16KB) per stage
#define FLASH_SMEM (32768 + 3 * FKV_STG)   // 128KB

__device__ __forceinline__ void fa_load_kv_h(
    uint32_t smBase, int stage,
    const __half* __restrict__ Kp, const __half* __restrict__ Vtp,
    int kcol0, int tid)
{
    const uint32_t kB = smBase + 32768 + stage * FKV_STG;
    const uint32_t vB = kB + 16384;
    #pragma unroll
    for (int i = 0; i < 4; i++) {
        int c = i * 256 + tid;
        {
            int row = c >> 4, cp = c & 15;
            cp16s(kB + OFF256(row, cp), Kp + (size_t)row * D_ + cp * 8);
        }
        {
            int row = c >> 3, cp = c & 7;
            cp16s(vB + OFF128(row, cp), Vtp + (size_t)row * S_ + kcol0 + cp * 8);
        }
    }
    CP_COMMIT();
}

__global__ __launch_bounds__(256, 1) void flash_f16(
    const __half* __restrict__ Qb, const __half* __restrict__ Kc,
    const __half* __restrict__ Vc, __half* __restrict__ AO)
{
    extern __shared__ __align__(128) uint8_t smraw[];
    const uint32_t smBase = smem_u32(smraw);

    const int qt = (S_ / 128 - 1) - blockIdx.x;
    const int bh = blockIdx.y;
    const int b = bh / HQ_, h = bh % HQ_;
    const int kvh = h / (HQ_ / HKV_);
    const int m0 = qt * 128;

    const int tid = threadIdx.x, lane = tid & 31, warp = tid >> 5;
    const int g = lane >> 2, t = lane & 3;
    const int l7 = lane & 7, lhi = lane >> 4, lb3 = (lane >> 3) & 1;

    const __half* Qbase = Qb + (size_t)(b * HQ_ + h) * S_ * D_ + (size_t)m0 * D_;
    const __half* Kbase = Kc + (size_t)(b * HKV_ + kvh) * S_ * D_;
    const __half* Vtb   = Vc + (size_t)(b * HKV_ + kvh) * D_ * S_;

    #pragma unroll
    for (int i = 0; i < 8; i++) {
        int c = i * 256 + tid;
        int row = c >> 4, cp = c & 15;
        cp16s(smBase + SMQ_OFF + OFF256(row, cp), Qbase + (size_t)row * D_ + cp * 8);
    }
    CP_COMMIT();

    const int nkt = 2 * qt + 2;
    fa_load_kv_h(smBase, 0, Kbase, Vtb, 0, tid);
    if (nkt > 1)
        fa_load_kv_h(smBase, 1, Kbase + (size_t)64 * D_, Vtb, 64, tid);

    uint32_t qf[8][4];
    float Oacc[16][4] = {};
    float mrow0 = -FLT_MAX, mrow1 = -FLT_MAX;
    float lrow0 = 0.f, lrow1 = 0.f;

    for (int kt = 0; kt < nkt; kt++) {
        const int s = kt % 3;
        if (kt + 1 < nkt) { CP_WAIT(1); } else { CP_WAIT(0); }
        __syncthreads();
        if (kt + 2 < nkt)
            fa_load_kv_h(smBase, (kt + 2) % 3, Kbase + (size_t)(kt + 2) * 64 * D_,
                         Vtb, (kt + 2) * 64, tid);

        if (kt == 0) {
            const int qrow = warp * 16 + (lane & 15);
            #pragma unroll
            for (int ks = 0; ks < 8; ks++) {
                int ch = 2 * ks + lhi;
                ldsm_x4(qf[ks], smBase + SMQ_OFF + OFF256(qrow, ch));
            }
        }

        const uint32_t kB = smBase + 32768 + s * FKV_STG;
        const uint32_t vB = kB + 16384;

        float sc[8][4];
        #pragma unroll
        for (int nf = 0; nf < 8; nf++)
            sc[nf][0] = sc[nf][1] = sc[nf][2] = sc[nf][3] = 0.f;
        #pragma unroll
        for (int ks = 0; ks < 8; ks++) {
            #pragma unroll
            for (int nfp = 0; nfp < 4; nfp++) {
                int krow = nfp * 16 + lhi * 8 + l7;
                int ch   = 2 * ks + lb3;
                uint32_t bb[4];
                ldsm_x4(bb, kB + OFF256(krow, ch));
                mma_f16(sc[2 * nfp],     qf[ks], &bb[0]);
                mma_f16(sc[2 * nfp + 1], qf[ks], &bb[2]);
            }
        }

        const int r0 = m0 + warp * 16 + g;
        const int r1 = r0 + 8;
        if (kt >= 2 * qt) {
            #pragma unroll
            for (int nf = 0; nf < 8; nf++) {
                int c0 = kt * 64 + nf * 8 + 2 * t;
                if (c0     > r0) sc[nf][0] = -FLT_MAX;
                if (c0 + 1 > r0) sc[nf][1] = -FLT_MAX;
                if (c0     > r1) sc[nf][2] = -FLT_MAX;
                if (c0 + 1 > r1) sc[nf][3] = -FLT_MAX;
            }
        }

        float mx0 = -FLT_MAX, mx1 = -FLT_MAX;
        #pragma unroll
        for (int nf = 0; nf < 8; nf++) {
            mx0 = fmaxf(mx0, fmaxf(sc[nf][0], sc[nf][1]));
            mx1 = fmaxf(mx1, fmaxf(sc[nf][2], sc[nf][3]));
        }
        mx0 = fmaxf(mx0, __shfl_xor_sync(0xffffffffu, mx0, 1));
        mx0 = fmaxf(mx0, __shfl_xor_sync(0xffffffffu, mx0, 2));
        mx1 = fmaxf(mx1, __shfl_xor_sync(0xffffffffu, mx1, 1));
        mx1 = fmaxf(mx1, __shfl_xor_sync(0xffffffffu, mx1, 2));

        float mnew0 = fmaxf(mrow0, mx0), mnew1 = fmaxf(mrow1, mx1);
        float f0 = ex2(mrow0 - mnew0), f1 = ex2(mrow1 - mnew1);
        mrow0 = mnew0; mrow1 = mnew1;

        float rs0 = 0.f, rs1 = 0.f;
        #pragma unroll
        for (int nf = 0; nf < 8; nf++) {
            sc[nf][0] = ex2(sc[nf][0] - mnew0);
            sc[nf][1] = ex2(sc[nf][1] - mnew0);
            sc[nf][2] = ex2(sc[nf][2] - mnew1);
            sc[nf][3] = ex2(sc[nf][3] - mnew1);
            rs0 += sc[nf][0] + sc[nf][1];
            rs1 += sc[nf][2] + sc[nf][3];
        }
        rs0 += __shfl_xor_sync(0xffffffffu, rs0, 1);
        rs0 += __shfl_xor_sync(0xffffffffu, rs0, 2);
        rs1 += __shfl_xor_sync(0xffffffffu, rs1, 1);
        rs1 += __shfl_xor_sync(0xffffffffu, rs1, 2);
        lrow0 = lrow0 * f0 + rs0;
        lrow1 = lrow1 * f1 + rs1;

        #pragma unroll
        for (int nf2 = 0; nf2 < 16; nf2++) {
            Oacc[nf2][0] *= f0; Oacc[nf2][1] *= f0;
            Oacc[nf2][2] *= f1; Oacc[nf2][3] *= f1;
        }

        #pragma unroll
        for (int kk = 0; kk < 4; kk++) {
            uint32_t aP[4];
            aP[0] = pack_h2(sc[2 * kk][0],     sc[2 * kk][1]);
            aP[1] = pack_h2(sc[2 * kk][2],     sc[2 * kk][3]);
            aP[2] = pack_h2(sc[2 * kk + 1][0], sc[2 * kk + 1][1]);
            aP[3] = pack_h2(sc[2 * kk + 1][2], sc[2 * kk + 1][3]);

            #pragma unroll
            for (int np = 0; np < 8; np++) {
                int vrow = np * 16 + lhi * 8 + l7;
                int ch   = 2 * kk + lb3;
                uint32_t bv4[4];
                ldsm_x4(bv4, vB + OFF128(vrow, ch));
                mma_f16(Oacc[2 * np],     aP, &bv4[0]);
                mma_f16(Oacc[2 * np + 1], aP, &bv4[2]);
            }
        }
    }

    const float inv0 = 1.0f / lrow0, inv1 = 1.0f / lrow1;
    const int r0 = m0 + warp * 16 + g;
    #pragma unroll
    for (int nf2 = 0; nf2 < 16; nf2++) {
        int cc = h * D_ + nf2 * 8 + 2 * t;
        __half* C0 = AO + (size_t)(b * S_ + r0) * (HQ_ * D_) + cc;
        __half* C1 = AO + (size_t)(b * S_ + r0 + 8) * (HQ_ * D_) + cc;
        *(__half2*)C0 = __floats2half2_rn(Oacc[nf2][0] * inv0, Oacc[nf2][1] * inv0);
        *(__half2*)C1 = __floats2half2_rn(Oacc[nf2][2] * inv1, Oacc[nf2][3] * inv1);
    }
}

// ---------------------------------------------------------------------------
// kernel_launch
// ---------------------------------------------------------------------------
extern "C" void kernel_launch(void* const* d_in, const int* in_sizes, int n_in,
                              void* d_out, int out_size) {
    const float* x  = (const float*)d_in[0];
    const int*   ip = (const int*)  d_in[1];
    const float* fc = (const float*)d_in[2];
    const float* wq = (const float*)d_in[3];
    const float* wk = (const float*)d_in[4];
    const float* wv = (const float*)d_in[5];
    const float* wo = (const float*)d_in[6];
    float* out = (float*)d_out;

    __half *xH, *wqT, *wkT, *wvT, *woT, *Qb, *Kc, *Vc, *AO;
    cudaGetSymbolAddress((void**)&xH,  g_xH);
    cudaGetSymbolAddress((void**)&wqT, g_wqT);
    cudaGetSymbolAddress((void**)&wkT, g_wkT);
    cudaGetSymbolAddress((void**)&wvT, g_wvT);
    cudaGetSymbolAddress((void**)&woT, g_woT);
    cudaGetSymbolAddress((void**)&Qb,  g_Qb);
    cudaGetSymbolAddress((void**)&Kc,  g_Kc);
    cudaGetSymbolAddress((void**)&Vc,  g_Vc);
    cudaGetSymbolAddress((void**)&AO,  g_AO);

    static int attr_set = 0;
    if (!attr_set) {
        cudaFuncSetAttribute(flash_f16, cudaFuncAttributeMaxDynamicSharedMemorySize, FLASH_SMEM);
        cudaFuncSetAttribute(gemm_f16<0>, cudaFuncAttributeMaxDynamicSharedMemorySize, GEMM_DSMEM);
        cudaFuncSetAttribute(gemm_f16<3>, cudaFuncAttributeMaxDynamicSharedMemorySize, GEMM_DSMEM);
        attr_set = 1;
    }

    // 0) pre-convert x (fp16); all 4 weight transposes in one launch
    const int n4_x = (M_ * E_) / 4;
    cvt_f16_arr<<<(n4_x + 255) / 256, 256>>>((const float4*)x, (uint2*)xH, n4_x);
    cvt_transpose_all<<<40960, dim3(32, 8)>>>(wq, wk, wv, wo, wqT, wkT, wvT, woT);

    // 1) Combined Q+K+V projection (one launch; Q/K/V by blockIdx.x)
    gemm_f16<3><<<dim3(48, M_ / 128), 256, GEMM_DSMEM>>>(
        xH, wqT, wkT, wvT, nullptr, Qb, Kc, Vc, fc, ip, M_, HQ_ * D_, E_);

    // 2) Fused flash attention
    flash_f16<<<dim3(S_ / 128, B_ * HQ_), 256, FLASH_SMEM>>>(Qb, Kc, Vc, AO);

    // 3) Output projection (fp32 out)
    gemm_f16<0><<<dim3(E_ / 128, M_ / 128), 256, GEMM_DSMEM>>>(
        AO, woT, nullptr, nullptr, out, nullptr, nullptr, nullptr, nullptr, nullptr,
        M_, E_, E_);
}

// round 16
// speedup vs baseline: 1.0922x; 1.0227x over previous
#include <cuda_runtime.h>
#include <cuda_fp16.h>
#include <float.h>
#include <math.h>
#include <stdint.h>

// Problem constants
#define B_   2
#define S_   2048
#define E_   4096
#define HQ_  32
#define HKV_ 8
#define D_   128
#define M_   (B_ * S_)          // 4096
#define SCALE_ 0.015625f        // 1/sqrt(4096)
#define LOG2E_ 1.44269504088896f

// ---------------------------------------------------------------------------
// Scratch
// ---------------------------------------------------------------------------
__device__ __half g_xH [(size_t)M_ * E_];             // x fp16 [M][K]
__device__ __half g_wqT[(size_t)(HQ_ * D_) * E_];     // wq^T [N][K]
__device__ __half g_wkT[(size_t)(HKV_ * D_) * E_];    // wk^T
__device__ __half g_wvT[(size_t)(HKV_ * D_) * E_];    // wv^T
__device__ __half g_woT[(size_t)E_ * (HQ_ * D_)];     // wo^T
__device__ __half g_Qb [(size_t)B_ * HQ_ * S_ * D_];  // roped+scaled(log2e) Q [b,h,s,d]
__device__ __half g_Kc [(size_t)B_ * HKV_ * S_ * D_]; // roped K cache   [b,h,pos,d]
__device__ __half g_Vc [(size_t)B_ * HKV_ * D_ * S_]; // V cache transposed [b,h,d,pos]
__device__ __half g_AO [(size_t)M_ * (HQ_ * D_)];     // attn out fp16

// ---------------------------------------------------------------------------
// helpers
// ---------------------------------------------------------------------------
__device__ __forceinline__ void mma_f16(float* c, const uint32_t* a, const uint32_t* b) {
    asm volatile(
        "mma.sync.aligned.m16n8k16.row.col.f32.f16.f16.f32 "
        "{%0,%1,%2,%3},{%4,%5,%6,%7},{%8,%9},{%0,%1,%2,%3};"
        : "+f"(c[0]), "+f"(c[1]), "+f"(c[2]), "+f"(c[3])
        : "r"(a[0]), "r"(a[1]), "r"(a[2]), "r"(a[3]), "r"(b[0]), "r"(b[1]));
}
__device__ __forceinline__ void ldsm_x4(uint32_t* r, uint32_t addr) {
    asm volatile("ldmatrix.sync.aligned.m8n8.x4.shared.b16 {%0,%1,%2,%3}, [%4];"
        : "=r"(r[0]), "=r"(r[1]), "=r"(r[2]), "=r"(r[3]) : "r"(addr));
}
__device__ __forceinline__ void cp16s(uint32_t saddr, const void* gmem) {
    asm volatile("cp.async.cg.shared.global [%0], [%1], 16;\n" :: "r"(saddr), "l"(gmem));
}
#define CP_COMMIT() asm volatile("cp.async.commit_group;\n" ::: "memory")
#define CP_WAIT(n)  asm volatile("cp.async.wait_group %0;\n" :: "n"(n) : "memory")
__device__ __forceinline__ uint32_t smem_u32(const void* p) {
    return (uint32_t)__cvta_generic_to_shared(p);
}
__device__ __forceinline__ uint32_t pack_h2(float a, float b) {
    __half2 h = __floats2half2_rn(a, b);
    return *(uint32_t*)&h;
}
__device__ __forceinline__ float ex2(float x) {
    float y;
    asm("ex2.approx.ftz.f32 %0, %1;" : "=f"(y) : "f"(x));
    return y;
}
// swizzled byte offsets (cp = 16B-chunk index within row)
#define OFF256(row, cp) ((uint32_t)((row) * 256 + (((((cp) & 7) ^ ((row) & 7)) | ((cp) & 8)) << 4)))
#define OFF128(row, cp) ((uint32_t)((row) * 128 + ((((cp) ^ ((row) & 7))) << 4)))

// ---------------------------------------------------------------------------
// Pre-pass: fp32 -> fp16 conversion of x; all 4 weight transposes in 1 launch
// ---------------------------------------------------------------------------
__global__ void cvt_f16_arr(const float4* __restrict__ in, uint2* __restrict__ out, int n4) {
    int i = blockIdx.x * 256 + threadIdx.x;
    if (i < n4) {
        float4 v = in[i];
        out[i] = make_uint2(pack_h2(v.x, v.y), pack_h2(v.z, v.w));
    }
}
__global__ void cvt_transpose_all(
    const float* __restrict__ wq, const float* __restrict__ wk,
    const float* __restrict__ wv, const float* __restrict__ wo,
    __half* __restrict__ oq, __half* __restrict__ ok,
    __half* __restrict__ ov, __half* __restrict__ oo)
{
    __shared__ __half tb[32][33];
    const int bid = blockIdx.x;
    const float* in;
    __half* out;
    int Kd, Nd, bx, by;
    if (bid < 16384)      { in = wq; out = oq; Kd = E_; Nd = HQ_ * D_;
                            int r = bid;          bx = (r & 127) * 32; by = (r >> 7) * 32; }
    else if (bid < 20480) { in = wk; out = ok; Kd = E_; Nd = HKV_ * D_;
                            int r = bid - 16384;  bx = (r & 31) * 32;  by = (r >> 5) * 32; }
    else if (bid < 24576) { in = wv; out = ov; Kd = E_; Nd = HKV_ * D_;
                            int r = bid - 20480;  bx = (r & 31) * 32;  by = (r >> 5) * 32; }
    else                  { in = wo; out = oo; Kd = HQ_ * D_; Nd = E_;
                            int r = bid - 24576;  bx = (r & 127) * 32; by = (r >> 7) * 32; }
    const int x = threadIdx.x, y = threadIdx.y;
    #pragma unroll
    for (int j = 0; j < 32; j += 8)
        tb[y + j][x] = __float2half(in[(size_t)(by + y + j) * Nd + bx + x]);
    __syncthreads();
    #pragma unroll
    for (int j = 0; j < 32; j += 8)
        out[(size_t)(bx + y + j) * Kd + by + x] = tb[x][y + j];
}

// ---------------------------------------------------------------------------
// fp16 GEMM (unchanged R14/R15 structure)
// ---------------------------------------------------------------------------
#define KCH 64
#define TILEB (128 * 128)
#define NSTG 3
#define GEMM_DSMEM (NSTG * 2 * TILEB)   // 96KB

template<int MODE>
__global__ __launch_bounds__(256, 2) void gemm_f16(
    const __half* __restrict__ A, const __half* __restrict__ Bq,
    const __half* __restrict__ Bk, const __half* __restrict__ Bv,
    float* __restrict__ C, __half* __restrict__ Oq, __half* __restrict__ Okk,
    __half* __restrict__ Ov,
    const float* __restrict__ fc, const int* __restrict__ ip,
    int M, int N, int K)
{
    extern __shared__ __align__(128) uint8_t dynraw[];
    const uint32_t smBase = smem_u32(dynraw);

    const int tid = threadIdx.x;
    const int lane = tid & 31, warp = tid >> 5;
    const int g = lane >> 2, t = lane & 3;
    const int wm = warp & 1, wn = warp >> 1;
    const int m0 = blockIdx.y * 128;

    const int l7 = lane & 7, l15 = lane & 15;
    const int lhi = lane >> 4, lb3 = (lane >> 3) & 1;

    const __half* Bt;
    int n0;
    int kind = 0;
    if (MODE == 3) {
        if (blockIdx.x < 32)      { Bt = Bq; n0 = blockIdx.x * 128;        kind = 0; }
        else if (blockIdx.x < 40) { Bt = Bk; n0 = (blockIdx.x - 32) * 128; kind = 1; }
        else                      { Bt = Bv; n0 = (blockIdx.x - 40) * 128; kind = 2; }
    } else {
        Bt = Bq; n0 = blockIdx.x * 128;
    }

    float acc[4][4][4] = {};

    auto load_chunk = [&](int ck, int st) {
        const uint32_t aB = smBase + st * TILEB;
        const uint32_t bB = smBase + NSTG * TILEB + st * TILEB;
        #pragma unroll
        for (int i = 0; i < 4; i++) {
            int c = i * 256 + tid;
            int row = c >> 3, cp = c & 7;
            uint32_t off = OFF128(row, cp);
            cp16s(aB + off, A  + (size_t)(m0 + row) * K + ck * KCH + cp * 8);
            cp16s(bB + off, Bt + (size_t)(n0 + row) * K + ck * KCH + cp * 8);
        }
        CP_COMMIT();
    };

    const int nchunk = K / KCH;
    load_chunk(0, 0);
    load_chunk(1, 1);

    for (int ci = 0; ci < nchunk; ci++) {
        const int s = ci % NSTG;
        if (ci + 1 < nchunk) { CP_WAIT(1); } else { CP_WAIT(0); }
        __syncthreads();
        if (ci + 2 < nchunk) load_chunk(ci + 2, (ci + 2) % NSTG);

        const uint32_t aB = smBase + s * TILEB;
        const uint32_t bB = smBase + NSTG * TILEB + s * TILEB;

        #pragma unroll
        for (int kk = 0; kk < 4; kk++) {
            uint32_t af[4][4], bf[2][4];
            #pragma unroll
            for (int mt = 0; mt < 4; mt++) {
                int row = wm * 64 + mt * 16 + l15;
                int ch  = 2 * kk + lhi;
                ldsm_x4(af[mt], aB + OFF128(row, ch));
            }
            #pragma unroll
            for (int p = 0; p < 2; p++) {
                int row = wn * 32 + p * 16 + lhi * 8 + l7;
                int ch  = 2 * kk + lb3;
                ldsm_x4(bf[p], bB + OFF128(row, ch));
            }
            #pragma unroll
            for (int mt = 0; mt < 4; mt++) {
                #pragma unroll
                for (int p = 0; p < 2; p++) {
                    mma_f16(acc[mt][2 * p],     af[mt], &bf[p][0]);
                    mma_f16(acc[mt][2 * p + 1], af[mt], &bf[p][2]);
                }
            }
        }
    }
    __syncthreads();

    if (MODE == 0) {
        #pragma unroll
        for (int mt = 0; mt < 4; mt++) {
            int r = m0 + wm * 64 + mt * 16 + g;
            #pragma unroll
            for (int nt = 0; nt < 4; nt++) {
                int cc = n0 + wn * 32 + nt * 8 + t * 2;
                *(float2*)(C + (size_t)r * N + cc)       = make_float2(acc[mt][nt][0], acc[mt][nt][1]);
                *(float2*)(C + (size_t)(r + 8) * N + cc) = make_float2(acc[mt][nt][2], acc[mt][nt][3]);
            }
        }
    } else {
        const bool doRope = (kind != 2);
        #pragma unroll
        for (int mt = 0; mt < 4; mt++) {
            int r = m0 + wm * 64 + mt * 16 + g;
            int b = r >> 11;
            int sA = r & (S_ - 1);
            int sB = sA + 8;
            #pragma unroll
            for (int nt = 0; nt < 4; nt++) {
                int cc = n0 + wn * 32 + nt * 8 + t * 2;
                int h  = cc >> 7;
                int dd = cc & (D_ - 1);
                int p  = dd >> 1;

                float a0 = acc[mt][nt][0], a1 = acc[mt][nt][1];
                float a2 = acc[mt][nt][2], a3 = acc[mt][nt][3];
                float o0, o1, o2, o3;
                if (doRope) {
                    float2 csA = ((const float2*)fc)[(size_t)sA * 64 + p];
                    float2 csB = ((const float2*)fc)[(size_t)sB * 64 + p];
                    o0 = a0 * csA.x - a1 * csA.y;
                    o1 = a0 * csA.y + a1 * csA.x;
                    o2 = a2 * csB.x - a3 * csB.y;
                    o3 = a2 * csB.y + a3 * csB.x;
                } else {
                    o0 = a0; o1 = a1; o2 = a2; o3 = a3;
                }

                if (kind == 0) {
                    const float sc2 = SCALE_ * LOG2E_;
                    o0 *= sc2; o1 *= sc2; o2 *= sc2; o3 *= sc2;
                    *(__half2*)(Oq + ((size_t)(b * HQ_ + h) * S_ + sA) * D_ + dd) = __floats2half2_rn(o0, o1);
                    *(__half2*)(Oq + ((size_t)(b * HQ_ + h) * S_ + sB) * D_ + dd) = __floats2half2_rn(o2, o3);
                } else if (kind == 1) {
                    int posA = ip[sA], posB = ip[sB];
                    *(__half2*)(Okk + ((size_t)(b * HKV_ + h) * S_ + posA) * D_ + dd) = __floats2half2_rn(o0, o1);
                    *(__half2*)(Okk + ((size_t)(b * HKV_ + h) * S_ + posB) * D_ + dd) = __floats2half2_rn(o2, o3);
                } else {
                    int posA = ip[sA], posB = ip[sB];
                    size_t base = (size_t)(b * HKV_ + h) * D_;
                    Ov[(base + dd)     * S_ + posA] = __float2half(o0);
                    Ov[(base + dd + 1) * S_ + posA] = __float2half(o1);
                    Ov[(base + dd)     * S_ + posB] = __float2half(o2);
                    Ov[(base + dd + 1) * S_ + posB] = __float2half(o3);
                }
            }
        }
    }
}

// ---------------------------------------------------------------------------
// Fused flash attention: 64-row Q tile, 4 warps, 2 CTAs/SM.
// exp2 softmax, 3-stage KV ring, one barrier per kt.
// ---------------------------------------------------------------------------
#define FQ_BYTES  16384                 // 64 rows x 256B
#define FKV_STG   32768                 // K(16KB) + V(16KB)
#define FLASH_SMEM (FQ_BYTES + 3 * FKV_STG)   // 112KB

__device__ __forceinline__ void fa_load_kv_h(
    uint32_t smBase, int stage,
    const __half* __restrict__ Kp, const __half* __restrict__ Vtp,
    int kcol0, int tid)
{
    const uint32_t kB = smBase + FQ_BYTES + stage * FKV_STG;
    const uint32_t vB = kB + 16384;
    #pragma unroll
    for (int i = 0; i < 8; i++) {
        int c = i * 128 + tid;
        {   // K: 64 rows x 16 chunks = 1024
            int row = c >> 4, cp = c & 15;
            cp16s(kB + OFF256(row, cp), Kp + (size_t)row * D_ + cp * 8);
        }
        {   // V^T: 128 rows x 8 chunks = 1024
            int row = c >> 3, cp = c & 7;
            cp16s(vB + OFF128(row, cp), Vtp + (size_t)row * S_ + kcol0 + cp * 8);
        }
    }
    CP_COMMIT();
}

__global__ __launch_bounds__(128, 2) void flash_f16(
    const __half* __restrict__ Qb, const __half* __restrict__ Kc,
    const __half* __restrict__ Vc, __half* __restrict__ AO)
{
    extern __shared__ __align__(128) uint8_t smraw[];
    const uint32_t smBase = smem_u32(smraw);

    const int qt = (S_ / 64 - 1) - blockIdx.x;   // 32 tiles, heavy first
    const int bh = blockIdx.y;
    const int b = bh / HQ_, h = bh % HQ_;
    const int kvh = h / (HQ_ / HKV_);
    const int m0 = qt * 64;

    const int tid = threadIdx.x, lane = tid & 31, warp = tid >> 5;   // 4 warps
    const int g = lane >> 2, t = lane & 3;
    const int l7 = lane & 7, lhi = lane >> 4, lb3 = (lane >> 3) & 1;

    const __half* Qbase = Qb + (size_t)(b * HQ_ + h) * S_ * D_ + (size_t)m0 * D_;
    const __half* Kbase = Kc + (size_t)(b * HKV_ + kvh) * S_ * D_;
    const __half* Vtb   = Vc + (size_t)(b * HKV_ + kvh) * D_ * S_;

    // stage Q tile: 64 rows x 16 chunks = 1024 cp16 over 128 threads
    #pragma unroll
    for (int i = 0; i < 8; i++) {
        int c = i * 128 + tid;
        int row = c >> 4, cp = c & 15;
        cp16s(smBase + OFF256(row, cp), Qbase + (size_t)row * D_ + cp * 8);
    }
    CP_COMMIT();

    const int nkt = qt + 1;
    fa_load_kv_h(smBase, 0, Kbase, Vtb, 0, tid);
    if (nkt > 1)
        fa_load_kv_h(smBase, 1, Kbase + (size_t)64 * D_, Vtb, 64, tid);

    uint32_t qf[8][4];
    float Oacc[16][4] = {};
    float mrow0 = -FLT_MAX, mrow1 = -FLT_MAX;
    float lrow0 = 0.f, lrow1 = 0.f;

    for (int kt = 0; kt < nkt; kt++) {
        const int s = kt % 3;
        if (kt + 1 < nkt) { CP_WAIT(1); } else { CP_WAIT(0); }
        __syncthreads();
        if (kt + 2 < nkt)
            fa_load_kv_h(smBase, (kt + 2) % 3, Kbase + (size_t)(kt + 2) * 64 * D_,
                         Vtb, (kt + 2) * 64, tid);

        if (kt == 0) {
            const int qrow = warp * 16 + (lane & 15);
            #pragma unroll
            for (int ks = 0; ks < 8; ks++) {
                int ch = 2 * ks + lhi;
                ldsm_x4(qf[ks], smBase + OFF256(qrow, ch));
            }
        }

        const uint32_t kB = smBase + FQ_BYTES + s * FKV_STG;
        const uint32_t vB = kB + 16384;

        float sc[8][4];
        #pragma unroll
        for (int nf = 0; nf < 8; nf++)
            sc[nf][0] = sc[nf][1] = sc[nf][2] = sc[nf][3] = 0.f;
        #pragma unroll
        for (int ks = 0; ks < 8; ks++) {
            #pragma unroll
            for (int nfp = 0; nfp < 4; nfp++) {
                int krow = nfp * 16 + lhi * 8 + l7;
                int ch   = 2 * ks + lb3;
                uint32_t bb[4];
                ldsm_x4(bb, kB + OFF256(krow, ch));
                mma_f16(sc[2 * nfp],     qf[ks], &bb[0]);
                mma_f16(sc[2 * nfp + 1], qf[ks], &bb[2]);
            }
        }

        const int r0 = m0 + warp * 16 + g;
        const int r1 = r0 + 8;
        if (kt == qt) {   // diagonal tile
            #pragma unroll
            for (int nf = 0; nf < 8; nf++) {
                int c0 = kt * 64 + nf * 8 + 2 * t;
                if (c0     > r0) sc[nf][0] = -FLT_MAX;
                if (c0 + 1 > r0) sc[nf][1] = -FLT_MAX;
                if (c0     > r1) sc[nf][2] = -FLT_MAX;
                if (c0 + 1 > r1) sc[nf][3] = -FLT_MAX;
            }
        }

        float mx0 = -FLT_MAX, mx1 = -FLT_MAX;
        #pragma unroll
        for (int nf = 0; nf < 8; nf++) {
            mx0 = fmaxf(mx0, fmaxf(sc[nf][0], sc[nf][1]));
            mx1 = fmaxf(mx1, fmaxf(sc[nf][2], sc[nf][3]));
        }
        mx0 = fmaxf(mx0, __shfl_xor_sync(0xffffffffu, mx0, 1));
        mx0 = fmaxf(mx0, __shfl_xor_sync(0xffffffffu, mx0, 2));
        mx1 = fmaxf(mx1, __shfl_xor_sync(0xffffffffu, mx1, 1));
        mx1 = fmaxf(mx1, __shfl_xor_sync(0xffffffffu, mx1, 2));

        float mnew0 = fmaxf(mrow0, mx0), mnew1 = fmaxf(mrow1, mx1);
        float f0 = ex2(mrow0 - mnew0), f1 = ex2(mrow1 - mnew1);
        mrow0 = mnew0; mrow1 = mnew1;

        float rs0 = 0.f, rs1 = 0.f;
        #pragma unroll
        for (int nf = 0; nf < 8; nf++) {
            sc[nf][0] = ex2(sc[nf][0] - mnew0);
            sc[nf][1] = ex2(sc[nf][1] - mnew0);
            sc[nf][2] = ex2(sc[nf][2] - mnew1);
            sc[nf][3] = ex2(sc[nf][3] - mnew1);
            rs0 += sc[nf][0] + sc[nf][1];
            rs1 += sc[nf][2] + sc[nf][3];
        }
        rs0 += __shfl_xor_sync(0xffffffffu, rs0, 1);
        rs0 += __shfl_xor_sync(0xffffffffu, rs0, 2);
        rs1 += __shfl_xor_sync(0xffffffffu, rs1, 1);
        rs1 += __shfl_xor_sync(0xffffffffu, rs1, 2);
        lrow0 = lrow0 * f0 + rs0;
        lrow1 = lrow1 * f1 + rs1;

        #pragma unroll
        for (int nf2 = 0; nf2 < 16; nf2++) {
            Oacc[nf2][0] *= f0; Oacc[nf2][1] *= f0;
            Oacc[nf2][2] *= f1; Oacc[nf2][3] *= f1;
        }

        #pragma unroll
        for (int kk = 0; kk < 4; kk++) {
            uint32_t aP[4];
            aP[0] = pack_h2(sc[2 * kk][0],     sc[2 * kk][1]);
            aP[1] = pack_h2(sc[2 * kk][2],     sc[2 * kk][3]);
            aP[2] = pack_h2(sc[2 * kk + 1][0], sc[2 * kk + 1][1]);
            aP[3] = pack_h2(sc[2 * kk + 1][2], sc[2 * kk + 1][3]);

            #pragma unroll
            for (int np = 0; np < 8; np++) {
                int vrow = np * 16 + lhi * 8 + l7;
                int ch   = 2 * kk + lb3;
                uint32_t bv4[4];
                ldsm_x4(bv4, vB + OFF128(vrow, ch));
                mma_f16(Oacc[2 * np],     aP, &bv4[0]);
                mma_f16(Oacc[2 * np + 1], aP, &bv4[2]);
            }
        }
    }

    const float inv0 = 1.0f / lrow0, inv1 = 1.0f / lrow1;
    const int r0 = m0 + warp * 16 + g;
    #pragma unroll
    for (int nf2 = 0; nf2 < 16; nf2++) {
        int cc = h * D_ + nf2 * 8 + 2 * t;
        __half* C0 = AO + (size_t)(b * S_ + r0) * (HQ_ * D_) + cc;
        __half* C1 = AO + (size_t)(b * S_ + r0 + 8) * (HQ_ * D_) + cc;
        *(__half2*)C0 = __floats2half2_rn(Oacc[nf2][0] * inv0, Oacc[nf2][1] * inv0);
        *(__half2*)C1 = __floats2half2_rn(Oacc[nf2][2] * inv1, Oacc[nf2][3] * inv1);
    }
}

// ---------------------------------------------------------------------------
// kernel_launch
// ---------------------------------------------------------------------------
extern "C" void kernel_launch(void* const* d_in, const int* in_sizes, int n_in,
                              void* d_out, int out_size) {
    const float* x  = (const float*)d_in[0];
    const int*   ip = (const int*)  d_in[1];
    const float* fc = (const float*)d_in[2];
    const float* wq = (const float*)d_in[3];
    const float* wk = (const float*)d_in[4];
    const float* wv = (const float*)d_in[5];
    const float* wo = (const float*)d_in[6];
    float* out = (float*)d_out;

    __half *xH, *wqT, *wkT, *wvT, *woT, *Qb, *Kc, *Vc, *AO;
    cudaGetSymbolAddress((void**)&xH,  g_xH);
    cudaGetSymbolAddress((void**)&wqT, g_wqT);
    cudaGetSymbolAddress((void**)&wkT, g_wkT);
    cudaGetSymbolAddress((void**)&wvT, g_wvT);
    cudaGetSymbolAddress((void**)&woT, g_woT);
    cudaGetSymbolAddress((void**)&Qb,  g_Qb);
    cudaGetSymbolAddress((void**)&Kc,  g_Kc);
    cudaGetSymbolAddress((void**)&Vc,  g_Vc);
    cudaGetSymbolAddress((void**)&AO,  g_AO);

    static int attr_set = 0;
    if (!attr_set) {
        cudaFuncSetAttribute(flash_f16, cudaFuncAttributeMaxDynamicSharedMemorySize, FLASH_SMEM);
        cudaFuncSetAttribute(gemm_f16<0>, cudaFuncAttributeMaxDynamicSharedMemorySize, GEMM_DSMEM);
        cudaFuncSetAttribute(gemm_f16<3>, cudaFuncAttributeMaxDynamicSharedMemorySize, GEMM_DSMEM);
        attr_set = 1;
    }

    // 0) pre-convert x (fp16); all 4 weight transposes in one launch
    const int n4_x = (M_ * E_) / 4;
    cvt_f16_arr<<<(n4_x + 255) / 256, 256>>>((const float4*)x, (uint2*)xH, n4_x);
    cvt_transpose_all<<<40960, dim3(32, 8)>>>(wq, wk, wv, wo, wqT, wkT, wvT, woT);

    // 1) Combined Q+K+V projection (one launch; Q/K/V by blockIdx.x)
    gemm_f16<3><<<dim3(48, M_ / 128), 256, GEMM_DSMEM>>>(
        xH, wqT, wkT, wvT, nullptr, Qb, Kc, Vc, fc, ip, M_, HQ_ * D_, E_);

    // 2) Fused flash attention (64-row Q tiles, 2 CTAs/SM)
    flash_f16<<<dim3(S_ / 64, B_ * HQ_), 128, FLASH_SMEM>>>(Qb, Kc, Vc, AO);

    // 3) Output projection (fp32 out)
    gemm_f16<0><<<dim3(E_ / 128, M_ / 128), 256, GEMM_DSMEM>>>(
        AO, woT, nullptr, nullptr, out, nullptr, nullptr, nullptr, nullptr, nullptr,
        M_, E_, E_);
}